// round 10
// baseline (speedup 1.0000x reference)
#include <cuda_runtime.h>
#include <cstdint>
#include <cstdio>

#define DMODEL 2048
#define NHEADS 16
#define HDIM   128
#define BATCH  2
#define SEQ    2048
#define MROWS  (BATCH*SEQ)   // 4096

// ---------------- scratch (device globals: allocation-free) ----------------
__device__ float g_q[(size_t)MROWS * DMODEL];
__device__ float g_k[(size_t)MROWS * DMODEL];
__device__ float g_v[(size_t)MROWS * DMODEL];
__device__ float g_att[(size_t)MROWS * DMODEL];

// ---------------- helpers ----------------
__device__ __forceinline__ uint32_t f2tf(float x) {
    uint32_t r;
    asm("cvt.rna.tf32.f32 %0, %1;" : "=r"(r) : "f"(x));
    return r;
}

__device__ __forceinline__ void mma_tf32(float* c, const uint32_t* a, const uint32_t* b) {
    asm("mma.sync.aligned.m16n8k8.row.col.f32.tf32.tf32.f32 "
        "{%0,%1,%2,%3}, {%4,%5,%6,%7}, {%8,%9}, {%0,%1,%2,%3};"
        : "+f"(c[0]), "+f"(c[1]), "+f"(c[2]), "+f"(c[3])
        : "r"(a[0]), "r"(a[1]), "r"(a[2]), "r"(a[3]),
          "r"(b[0]), "r"(b[1]));
}

__device__ __forceinline__ void cpa16(uint32_t dst, const void* src) {
    asm volatile("cp.async.cg.shared.global [%0], [%1], 16;" :: "r"(dst), "l"(src));
}
__device__ __forceinline__ void cpa_commit() {
    asm volatile("cp.async.commit_group;" ::: "memory");
}
__device__ __forceinline__ void cpa_wait0() {
    asm volatile("cp.async.wait_group 0;" ::: "memory");
}
__device__ __forceinline__ void cpa_wait1() {
    asm volatile("cp.async.wait_group 1;" ::: "memory");
}

// ---------------- GEMM body: C = (A @ W^T + bias) * scale ----------------
// CTA tile 128x128, k-tile 32, 8 warps (2x4), warp tile 64x32, m16n8k8 tf32.
// Double-buffered smem: ONE __syncthreads per k-iter.
#define GT_K 32
#define GLD  36                 // 32 + 4 pad
#define GSTG (128*GLD)          // words per matrix per stage
#define GEMM_SMEM_BYTES (4*GSTG*4)   // As0,Ws0,As1,Ws1 = 73728 B

template<bool ROUND>
__device__ __forceinline__ void gemm_body(
    const float* __restrict__ A, const float* __restrict__ W,
    const float* __restrict__ bias, float* __restrict__ C, float scale)
{
    extern __shared__ uint32_t gsm[];

    const int tid  = threadIdx.x;
    const int ctaN = blockIdx.x * 128;
    const int ctaM = blockIdx.y * 128;

    const int warp = tid >> 5, lane = tid & 31;
    const int g = lane >> 2, tg = lane & 3;
    const int wm = (warp & 1) * 64;
    const int wn = (warp >> 1) * 32;

    const int lr = tid >> 3;        // 0..31
    const int lc = (tid & 7) * 4;   // 0..28

    const float* Abase = A + (size_t)(ctaM + lr) * DMODEL + lc;
    const float* Wbase = W + (size_t)(ctaN + lr) * DMODEL + lc;

    float acc[4][4][4];
#pragma unroll
    for (int mt = 0; mt < 4; mt++)
#pragma unroll
        for (int nt = 0; nt < 4; nt++)
#pragma unroll
            for (int j = 0; j < 4; j++) acc[mt][nt][j] = 0.f;

    const int nk = DMODEL / GT_K;

    // preload tile 0 into stage 0
    {
        uint32_t* As0 = gsm;
        uint32_t* Ws0 = gsm + GSTG;
#pragma unroll
        for (int p = 0; p < 4; p++) {
            float4 va = *(const float4*)(Abase + (size_t)(p * 32) * DMODEL);
            float4 vw = *(const float4*)(Wbase + (size_t)(p * 32) * DMODEL);
            *(uint4*)&As0[(lr + p * 32) * GLD + lc] =
                make_uint4(f2tf(va.x), f2tf(va.y), f2tf(va.z), f2tf(va.w));
            *(uint4*)&Ws0[(lr + p * 32) * GLD + lc] =
                make_uint4(f2tf(vw.x), f2tf(vw.y), f2tf(vw.z), f2tf(vw.w));
        }
    }
    __syncthreads();

    for (int kt = 0; kt < nk; kt++) {
        const int cur = kt & 1;
        const uint32_t* Asb = gsm + cur * 2 * GSTG;
        const uint32_t* Wsb = Asb + GSTG;

        float4 pa[4], pw[4];
        const bool pre = (kt + 1 < nk);
        if (pre) {
            const float* An = Abase + (size_t)(kt + 1) * GT_K;
            const float* Wn = Wbase + (size_t)(kt + 1) * GT_K;
#pragma unroll
            for (int p = 0; p < 4; p++) {
                pa[p] = *(const float4*)(An + (size_t)(p * 32) * DMODEL);
                pw[p] = *(const float4*)(Wn + (size_t)(p * 32) * DMODEL);
            }
        }

#pragma unroll
        for (int ks = 0; ks < 4; ks++) {
            uint32_t a[4][4];
#pragma unroll
            for (int mt = 0; mt < 4; mt++) {
                int r = wm + mt * 16 + g;
                int c = ks * 8 + tg;
                a[mt][0] = Asb[r * GLD + c];
                a[mt][1] = Asb[(r + 8) * GLD + c];
                a[mt][2] = Asb[r * GLD + c + 4];
                a[mt][3] = Asb[(r + 8) * GLD + c + 4];
            }
            uint32_t bfr[4][2];
#pragma unroll
            for (int nt = 0; nt < 4; nt++) {
                int rn = wn + nt * 8 + g;
                bfr[nt][0] = Wsb[rn * GLD + ks * 8 + tg];
                bfr[nt][1] = Wsb[rn * GLD + ks * 8 + tg + 4];
            }
#pragma unroll
            for (int mt = 0; mt < 4; mt++)
#pragma unroll
                for (int nt = 0; nt < 4; nt++)
                    mma_tf32(acc[mt][nt], a[mt], bfr[nt]);
        }

        if (pre) {
            uint32_t* And = gsm + (cur ^ 1) * 2 * GSTG;
            uint32_t* Wnd = And + GSTG;
#pragma unroll
            for (int p = 0; p < 4; p++) {
                *(uint4*)&And[(lr + p * 32) * GLD + lc] =
                    make_uint4(f2tf(pa[p].x), f2tf(pa[p].y), f2tf(pa[p].z), f2tf(pa[p].w));
                *(uint4*)&Wnd[(lr + p * 32) * GLD + lc] =
                    make_uint4(f2tf(pw[p].x), f2tf(pw[p].y), f2tf(pw[p].z), f2tf(pw[p].w));
            }
        }
        __syncthreads();
    }

    // epilogue: bias + scale; optionally round outputs to tf32 (for q/k/v scratch)
#pragma unroll
    for (int mt = 0; mt < 4; mt++) {
        int r0 = ctaM + wm + mt * 16 + g;
        int r1 = r0 + 8;
#pragma unroll
        for (int nt = 0; nt < 4; nt++) {
            int c = ctaN + wn + nt * 8 + 2 * tg;
            float b0 = bias[c], b1 = bias[c + 1];
            float v00 = (acc[mt][nt][0] + b0) * scale;
            float v01 = (acc[mt][nt][1] + b1) * scale;
            float v10 = (acc[mt][nt][2] + b0) * scale;
            float v11 = (acc[mt][nt][3] + b1) * scale;
            if (ROUND) {
                v00 = __uint_as_float(f2tf(v00));
                v01 = __uint_as_float(f2tf(v01));
                v10 = __uint_as_float(f2tf(v10));
                v11 = __uint_as_float(f2tf(v11));
            }
            *(float2*)&C[(size_t)r0 * DMODEL + c] = make_float2(v00, v01);
            *(float2*)&C[(size_t)r1 * DMODEL + c] = make_float2(v10, v11);
        }
    }
}

// Fused Q/K/V projections: blockIdx.z selects which projection. Outputs tf32-rounded.
__global__ void __launch_bounds__(256, 1) gemm_qkv(
    const float* __restrict__ q_in, const float* __restrict__ k_in, const float* __restrict__ v_in,
    const float* __restrict__ Wq, const float* __restrict__ bq,
    const float* __restrict__ Wk, const float* __restrict__ bk,
    const float* __restrict__ Wv, const float* __restrict__ bv,
    float* __restrict__ Cq, float* __restrict__ Ck, float* __restrict__ Cv,
    float qscale)
{
    const int z = blockIdx.z;
    const float* A   = (z == 0) ? q_in : (z == 1) ? k_in : v_in;
    const float* W   = (z == 0) ? Wq   : (z == 1) ? Wk   : Wv;
    const float* bia = (z == 0) ? bq   : (z == 1) ? bk   : bv;
    float*       C   = (z == 0) ? Cq   : (z == 1) ? Ck   : Cv;
    float        s   = (z == 0) ? qscale : 1.0f;
    gemm_body<true>(A, W, bia, C, s);
}

__global__ void __launch_bounds__(256, 1) gemm_o(
    const float* __restrict__ A, const float* __restrict__ W,
    const float* __restrict__ bias, float* __restrict__ C)
{
    gemm_body<false>(A, W, bias, C, 1.0f);
}

// ---------------- Flash attention (per (b,h,qtile=128)), tf32 mma ----------------
// Q/K/V in gmem are already tf32-rounded -> cp.async straight into smem, no cvt.
// Pipeline: K refill issued after S-MMA (hidden by softmax+PV); V refill after PV
// (hidden by next S-MMA). Alternating commit groups, wait_group 1.
#define ALD 132   // 128 + 4 pad
#define PLD 68    // 64 + 4 pad
#define KS_OFF (128*ALD)
#define VS_OFF (128*ALD + 64*ALD)
#define PS_OFF (128*ALD + 128*ALD)
#define ATT_SMEM_WORDS (PS_OFF + 128*PLD)
#define ATT_SMEM_BYTES (ATT_SMEM_WORDS * 4)
#define NKT (SEQ/64)

__global__ void __launch_bounds__(256, 1) attn_kernel(
    const float* __restrict__ Q, const float* __restrict__ Kp,
    const float* __restrict__ Vp, float* __restrict__ O)
{
    extern __shared__ uint32_t sm[];
    uint32_t (*Qs)[ALD] = (uint32_t(*)[ALD])sm;
    uint32_t (*Ks)[ALD] = (uint32_t(*)[ALD])(sm + KS_OFF);
    uint32_t (*Vs)[ALD] = (uint32_t(*)[ALD])(sm + VS_OFF);
    uint32_t (*Ps)[PLD] = (uint32_t(*)[PLD])(sm + PS_OFF);

    const uint32_t sbase = (uint32_t)__cvta_generic_to_shared(sm);

    const int tid  = threadIdx.x;
    const int qt = blockIdx.x, h = blockIdx.y, b = blockIdx.z;
    const int warp = tid >> 5, lane = tid & 31, g = lane >> 2, tg = lane & 3;
    const int qbase = warp * 16;

    const size_t rowQ0 = (size_t)(b * SEQ + qt * 128);
    const int colH = h * HDIM;

    const int ldr = tid >> 5;       // 0..7
    const int ldc = lane * 4;       // 0..124 (words)

    // prologue: async-copy Q (128 rows), K0, V0 — one group
#pragma unroll
    for (int p = 0; p < 16; p++) {
        int rr = ldr + p * 8;
        cpa16(sbase + 4u * (rr * ALD + ldc), Q + (rowQ0 + rr) * DMODEL + colH + ldc);
    }
    {
        size_t rowK0 = (size_t)(b * SEQ);
#pragma unroll
        for (int p = 0; p < 8; p++) {
            int rr = ldr + p * 8;
            cpa16(sbase + 4u * (KS_OFF + rr * ALD + ldc), Kp + (rowK0 + rr) * DMODEL + colH + ldc);
            cpa16(sbase + 4u * (VS_OFF + rr * ALD + ldc), Vp + (rowK0 + rr) * DMODEL + colH + ldc);
        }
    }
    cpa_commit();
    cpa_wait0();
    __syncthreads();

    float acc[16][4];
#pragma unroll
    for (int nt = 0; nt < 16; nt++)
#pragma unroll
        for (int j = 0; j < 4; j++) acc[nt][j] = 0.f;

    float m0 = -1e30f, m1 = -1e30f, l0 = 0.f, l1 = 0.f;

    for (int kt = 0; kt < NKT; kt++) {
        const bool pre = (kt + 1 < NKT);
        const size_t rowKn = (size_t)(b * SEQ + (kt + 1) * 64);

        // S = Q * K^T  (M=16 per warp, N=64, K=128); 1/sqrt(dh) folded into Q
        float sf[8][4];
#pragma unroll
        for (int nt = 0; nt < 8; nt++)
#pragma unroll
            for (int j = 0; j < 4; j++) sf[nt][j] = 0.f;

#pragma unroll
        for (int ks = 0; ks < 16; ks++) {
            uint32_t a[4];
            a[0] = Qs[qbase + g][ks * 8 + tg];
            a[1] = Qs[qbase + g + 8][ks * 8 + tg];
            a[2] = Qs[qbase + g][ks * 8 + tg + 4];
            a[3] = Qs[qbase + g + 8][ks * 8 + tg + 4];
#pragma unroll
            for (int nt = 0; nt < 8; nt++) {
                uint32_t bb[2];
                bb[0] = Ks[nt * 8 + g][ks * 8 + tg];
                bb[1] = Ks[nt * 8 + g][ks * 8 + tg + 4];
                mma_tf32(sf[nt], a, bb);
            }
        }

        // Ks free -> refill with next K tile (hidden by softmax + PV below)
        __syncthreads();
        if (pre) {
#pragma unroll
            for (int p = 0; p < 8; p++) {
                int rr = ldr + p * 8;
                cpa16(sbase + 4u * (KS_OFF + rr * ALD + ldc),
                      Kp + (rowKn + rr) * DMODEL + colH + ldc);
            }
            cpa_commit();
            cpa_wait1();   // current V tile (older group) is complete
        } else {
            cpa_wait0();
        }
        __syncthreads();

        // ---- online softmax (rows qbase+g and qbase+g+8) ----
        float tm0 = -1e30f, tm1 = -1e30f;
#pragma unroll
        for (int nt = 0; nt < 8; nt++) {
            tm0 = fmaxf(tm0, fmaxf(sf[nt][0], sf[nt][1]));
            tm1 = fmaxf(tm1, fmaxf(sf[nt][2], sf[nt][3]));
        }
        tm0 = fmaxf(tm0, __shfl_xor_sync(0xffffffffu, tm0, 1));
        tm0 = fmaxf(tm0, __shfl_xor_sync(0xffffffffu, tm0, 2));
        tm1 = fmaxf(tm1, __shfl_xor_sync(0xffffffffu, tm1, 1));
        tm1 = fmaxf(tm1, __shfl_xor_sync(0xffffffffu, tm1, 2));

        float nm0 = fmaxf(m0, tm0), nm1 = fmaxf(m1, tm1);
        float al0 = __expf(m0 - nm0), al1 = __expf(m1 - nm1);

        float ts0 = 0.f, ts1 = 0.f;
#pragma unroll
        for (int nt = 0; nt < 8; nt++) {
            sf[nt][0] = __expf(sf[nt][0] - nm0); ts0 += sf[nt][0];
            sf[nt][1] = __expf(sf[nt][1] - nm0); ts0 += sf[nt][1];
            sf[nt][2] = __expf(sf[nt][2] - nm1); ts1 += sf[nt][2];
            sf[nt][3] = __expf(sf[nt][3] - nm1); ts1 += sf[nt][3];
        }
        ts0 += __shfl_xor_sync(0xffffffffu, ts0, 1);
        ts0 += __shfl_xor_sync(0xffffffffu, ts0, 2);
        ts1 += __shfl_xor_sync(0xffffffffu, ts1, 1);
        ts1 += __shfl_xor_sync(0xffffffffu, ts1, 2);

        l0 = l0 * al0 + ts0;  l1 = l1 * al1 + ts1;
        m0 = nm0;             m1 = nm1;

#pragma unroll
        for (int nt = 0; nt < 16; nt++) {
            acc[nt][0] *= al0; acc[nt][1] *= al0;
            acc[nt][2] *= al1; acc[nt][3] *= al1;
        }

        // write P tile (warp-private rows) as tf32
#pragma unroll
        for (int nt = 0; nt < 8; nt++) {
            Ps[qbase + g][nt * 8 + 2 * tg]         = f2tf(sf[nt][0]);
            Ps[qbase + g][nt * 8 + 2 * tg + 1]     = f2tf(sf[nt][1]);
            Ps[qbase + g + 8][nt * 8 + 2 * tg]     = f2tf(sf[nt][2]);
            Ps[qbase + g + 8][nt * 8 + 2 * tg + 1] = f2tf(sf[nt][3]);
        }
        __syncwarp();

        // acc += P @ V  (M=16, N=128, K=64)
#pragma unroll
        for (int ks = 0; ks < 8; ks++) {
            uint32_t a[4];
            a[0] = Ps[qbase + g][ks * 8 + tg];
            a[1] = Ps[qbase + g + 8][ks * 8 + tg];
            a[2] = Ps[qbase + g][ks * 8 + tg + 4];
            a[3] = Ps[qbase + g + 8][ks * 8 + tg + 4];
#pragma unroll
            for (int nt = 0; nt < 16; nt++) {
                uint32_t bb[2];
                bb[0] = Vs[ks * 8 + tg][nt * 8 + g];
                bb[1] = Vs[ks * 8 + tg + 4][nt * 8 + g];
                mma_tf32(acc[nt], a, bb);
            }
        }

        // Vs free -> refill with next V tile (hidden by next iteration's S-MMA)
        __syncthreads();
        if (pre) {
#pragma unroll
            for (int p = 0; p < 8; p++) {
                int rr = ldr + p * 8;
                cpa16(sbase + 4u * (VS_OFF + rr * ALD + ldc),
                      Vp + (rowKn + rr) * DMODEL + colH + ldc);
            }
            cpa_commit();
            cpa_wait1();   // next K tile (older group) is complete
        } else {
            cpa_wait0();
        }
        __syncthreads();
    }

    // epilogue: normalize, write to [B*S, D] at head column
    float inv0 = 1.f / l0, inv1 = 1.f / l1;
    size_t r0 = rowQ0 + qbase + g;
    size_t r1 = r0 + 8;
#pragma unroll
    for (int nt = 0; nt < 16; nt++) {
        int c = colH + nt * 8 + 2 * tg;
        *(float2*)&O[r0 * DMODEL + c] = make_float2(acc[nt][0] * inv0, acc[nt][1] * inv0);
        *(float2*)&O[r1 * DMODEL + c] = make_float2(acc[nt][2] * inv1, acc[nt][3] * inv1);
    }
}

// ---------------- launch ----------------
extern "C" void kernel_launch(void* const* d_in, const int* in_sizes, int n_in,
                              void* d_out, int out_size)
{
    const float* query  = (const float*)d_in[0];
    const float* key_in = (const float*)d_in[1];
    const float* value  = (const float*)d_in[2];
    const float* Wq = (const float*)d_in[3];
    const float* bq = (const float*)d_in[4];
    const float* Wk = (const float*)d_in[5];
    const float* bk = (const float*)d_in[6];
    const float* Wv = (const float*)d_in[7];
    const float* bv = (const float*)d_in[8];
    const float* Wo = (const float*)d_in[9];
    const float* bo = (const float*)d_in[10];
    float* out = (float*)d_out;

    float *gq, *gk, *gv, *ga;
    cudaGetSymbolAddress((void**)&gq, g_q);
    cudaGetSymbolAddress((void**)&gk, g_k);
    cudaGetSymbolAddress((void**)&gv, g_v);
    cudaGetSymbolAddress((void**)&ga, g_att);

    cudaFuncSetAttribute(attn_kernel,
                         cudaFuncAttributeMaxDynamicSharedMemorySize, ATT_SMEM_BYTES);
    cudaFuncSetAttribute(gemm_qkv,
                         cudaFuncAttributeMaxDynamicSharedMemorySize, GEMM_SMEM_BYTES);
    cudaFuncSetAttribute(gemm_o,
                         cudaFuncAttributeMaxDynamicSharedMemorySize, GEMM_SMEM_BYTES);

    const float qscale = 0.08838834764831845f;   // 1/sqrt(128)

    dim3 qkv_grid(DMODEL / 128, MROWS / 128, 3);   // (16, 32, 3) = 1536 CTAs
    gemm_qkv<<<qkv_grid, 256, GEMM_SMEM_BYTES>>>(query, key_in, value,
                                                 Wq, bq, Wk, bk, Wv, bv,
                                                 gq, gk, gv, qscale);

    attn_kernel<<<dim3(SEQ / 128, NHEADS, BATCH), 256, ATT_SMEM_BYTES>>>(gq, gk, gv, ga);

    gemm_o<<<dim3(DMODEL / 128, MROWS / 128), 256, GEMM_SMEM_BYTES>>>(ga, Wo, bo, out);
}

// round 11
// speedup vs baseline: 1.0924x; 1.0924x over previous
#include <cuda_runtime.h>
#include <cstdint>
#include <cstdio>

#define DMODEL 2048
#define NHEADS 16
#define HDIM   128
#define BATCH  2
#define SEQ    2048
#define MROWS  (BATCH*SEQ)   // 4096

// ---------------- scratch (device globals: allocation-free) ----------------
__device__ float g_q[(size_t)MROWS * DMODEL];
__device__ float g_k[(size_t)MROWS * DMODEL];
__device__ float g_v[(size_t)MROWS * DMODEL];
__device__ float g_att[(size_t)MROWS * DMODEL];

// ---------------- helpers ----------------
__device__ __forceinline__ uint32_t f2tf(float x) {
    uint32_t r;
    asm("cvt.rna.tf32.f32 %0, %1;" : "=r"(r) : "f"(x));
    return r;
}

__device__ __forceinline__ void mma_tf32(float* c, const uint32_t* a, const uint32_t* b) {
    asm("mma.sync.aligned.m16n8k8.row.col.f32.tf32.tf32.f32 "
        "{%0,%1,%2,%3}, {%4,%5,%6,%7}, {%8,%9}, {%0,%1,%2,%3};"
        : "+f"(c[0]), "+f"(c[1]), "+f"(c[2]), "+f"(c[3])
        : "r"(a[0]), "r"(a[1]), "r"(a[2]), "r"(a[3]),
          "r"(b[0]), "r"(b[1]));
}

// ldmatrix x4: four 8x8 b16 matrices; for tf32 each 32-bit element = 2 b16.
// Lane m = lane>>3 addresses matrix m's row (lane&7).
__device__ __forceinline__ void ldsm_x4(uint32_t* r, uint32_t addr) {
    asm volatile("ldmatrix.sync.aligned.m8n8.x4.shared.b16 {%0,%1,%2,%3}, [%4];"
        : "=r"(r[0]), "=r"(r[1]), "=r"(r[2]), "=r"(r[3]) : "r"(addr));
}

__device__ __forceinline__ void cpa16(uint32_t dst, const void* src) {
    asm volatile("cp.async.cg.shared.global [%0], [%1], 16;" :: "r"(dst), "l"(src));
}
__device__ __forceinline__ void cpa_commit() {
    asm volatile("cp.async.commit_group;" ::: "memory");
}
__device__ __forceinline__ void cpa_wait0() {
    asm volatile("cp.async.wait_group 0;" ::: "memory");
}
__device__ __forceinline__ void cpa_wait1() {
    asm volatile("cp.async.wait_group 1;" ::: "memory");
}

// ---------------- GEMM body: C = (A @ W^T + bias) * scale ----------------
// CTA tile 128x128, k-tile 32, 8 warps (2x4), warp tile 64x32, m16n8k8 tf32.
// Double-buffered smem, ldmatrix fragment loads.
#define GT_K 32
#define GLD  36                 // 32 + 4 pad (stride%32==4 -> conflict-free)
#define GSTG (128*GLD)          // words per matrix per stage
#define GEMM_SMEM_BYTES (4*GSTG*4)   // 73728 B

template<bool ROUND>
__device__ __forceinline__ void gemm_body(
    const float* __restrict__ A, const float* __restrict__ W,
    const float* __restrict__ bias, float* __restrict__ C, float scale)
{
    extern __shared__ uint32_t gsm[];
    const uint32_t sbase = (uint32_t)__cvta_generic_to_shared(gsm);

    const int tid  = threadIdx.x;
    const int ctaN = blockIdx.x * 128;
    const int ctaM = blockIdx.y * 128;

    const int warp = tid >> 5, lane = tid & 31;
    const int g = lane >> 2, tg = lane & 3;
    const int wm = (warp & 1) * 64;
    const int wn = (warp >> 1) * 32;

    // ldmatrix per-lane addressing (tf32-as-2xb16):
    // A x4: m0=(rows wm+mt16+0..7, cols ks8+0..3) m1=rows+8 m2=cols+4 m3=rows+8,cols+4
    const int rowA = wm + (lane & 7) + ((lane & 8) ? 8 : 0);
    const int colA = (lane & 16) ? 4 : 0;
    // B x4 covers nt pair: m0=(rows wn+nt8, cols) m1=(cols+4) m2=(rows+8) m3=(rows+8,cols+4)
    const int rowB = wn + (lane & 7) + ((lane & 16) ? 8 : 0);
    const int colB = (lane & 8) ? 4 : 0;

    const int lr = tid >> 3;        // 0..31
    const int lc = (tid & 7) * 4;   // 0..28

    const float* Abase = A + (size_t)(ctaM + lr) * DMODEL + lc;
    const float* Wbase = W + (size_t)(ctaN + lr) * DMODEL + lc;

    float acc[4][4][4];
#pragma unroll
    for (int mt = 0; mt < 4; mt++)
#pragma unroll
        for (int nt = 0; nt < 4; nt++)
#pragma unroll
            for (int j = 0; j < 4; j++) acc[mt][nt][j] = 0.f;

    const int nk = DMODEL / GT_K;

    // preload tile 0 into stage 0
    {
        uint32_t* As0 = gsm;
        uint32_t* Ws0 = gsm + GSTG;
#pragma unroll
        for (int p = 0; p < 4; p++) {
            float4 va = *(const float4*)(Abase + (size_t)(p * 32) * DMODEL);
            float4 vw = *(const float4*)(Wbase + (size_t)(p * 32) * DMODEL);
            *(uint4*)&As0[(lr + p * 32) * GLD + lc] =
                make_uint4(f2tf(va.x), f2tf(va.y), f2tf(va.z), f2tf(va.w));
            *(uint4*)&Ws0[(lr + p * 32) * GLD + lc] =
                make_uint4(f2tf(vw.x), f2tf(vw.y), f2tf(vw.z), f2tf(vw.w));
        }
    }
    __syncthreads();

    for (int kt = 0; kt < nk; kt++) {
        const int cur = kt & 1;
        const uint32_t sA = sbase + (uint32_t)(cur * 2 * GSTG) * 4u;
        const uint32_t sW = sA + (uint32_t)GSTG * 4u;

        float4 pa[4], pw[4];
        const bool pre = (kt + 1 < nk);
        if (pre) {
            const float* An = Abase + (size_t)(kt + 1) * GT_K;
            const float* Wn = Wbase + (size_t)(kt + 1) * GT_K;
#pragma unroll
            for (int p = 0; p < 4; p++) {
                pa[p] = *(const float4*)(An + (size_t)(p * 32) * DMODEL);
                pw[p] = *(const float4*)(Wn + (size_t)(p * 32) * DMODEL);
            }
        }

#pragma unroll
        for (int ks = 0; ks < 4; ks++) {
            uint32_t a[4][4];
#pragma unroll
            for (int mt = 0; mt < 4; mt++)
                ldsm_x4(a[mt], sA + 4u * ((rowA + mt * 16) * GLD + ks * 8 + colA));
            uint32_t bfr[4][2];
#pragma unroll
            for (int ntp = 0; ntp < 2; ntp++) {
                uint32_t t[4];
                ldsm_x4(t, sW + 4u * ((rowB + ntp * 16) * GLD + ks * 8 + colB));
                bfr[2 * ntp][0] = t[0];  bfr[2 * ntp][1] = t[1];
                bfr[2 * ntp + 1][0] = t[2];  bfr[2 * ntp + 1][1] = t[3];
            }
#pragma unroll
            for (int mt = 0; mt < 4; mt++)
#pragma unroll
                for (int nt = 0; nt < 4; nt++)
                    mma_tf32(acc[mt][nt], a[mt], bfr[nt]);
        }

        if (pre) {
            uint32_t* And = gsm + (cur ^ 1) * 2 * GSTG;
            uint32_t* Wnd = And + GSTG;
#pragma unroll
            for (int p = 0; p < 4; p++) {
                *(uint4*)&And[(lr + p * 32) * GLD + lc] =
                    make_uint4(f2tf(pa[p].x), f2tf(pa[p].y), f2tf(pa[p].z), f2tf(pa[p].w));
                *(uint4*)&Wnd[(lr + p * 32) * GLD + lc] =
                    make_uint4(f2tf(pw[p].x), f2tf(pw[p].y), f2tf(pw[p].z), f2tf(pw[p].w));
            }
        }
        __syncthreads();
    }

    // epilogue: bias + scale; optionally round outputs to tf32 (for q/k/v scratch)
#pragma unroll
    for (int mt = 0; mt < 4; mt++) {
        int r0 = ctaM + wm + mt * 16 + g;
        int r1 = r0 + 8;
#pragma unroll
        for (int nt = 0; nt < 4; nt++) {
            int c = ctaN + wn + nt * 8 + 2 * tg;
            float b0 = bias[c], b1 = bias[c + 1];
            float v00 = (acc[mt][nt][0] + b0) * scale;
            float v01 = (acc[mt][nt][1] + b1) * scale;
            float v10 = (acc[mt][nt][2] + b0) * scale;
            float v11 = (acc[mt][nt][3] + b1) * scale;
            if (ROUND) {
                v00 = __uint_as_float(f2tf(v00));
                v01 = __uint_as_float(f2tf(v01));
                v10 = __uint_as_float(f2tf(v10));
                v11 = __uint_as_float(f2tf(v11));
            }
            *(float2*)&C[(size_t)r0 * DMODEL + c] = make_float2(v00, v01);
            *(float2*)&C[(size_t)r1 * DMODEL + c] = make_float2(v10, v11);
        }
    }
}

// Fused Q/K/V projections: blockIdx.z selects which projection. Outputs tf32-rounded.
__global__ void __launch_bounds__(256, 1) gemm_qkv(
    const float* __restrict__ q_in, const float* __restrict__ k_in, const float* __restrict__ v_in,
    const float* __restrict__ Wq, const float* __restrict__ bq,
    const float* __restrict__ Wk, const float* __restrict__ bk,
    const float* __restrict__ Wv, const float* __restrict__ bv,
    float* __restrict__ Cq, float* __restrict__ Ck, float* __restrict__ Cv,
    float qscale)
{
    const int z = blockIdx.z;
    const float* A   = (z == 0) ? q_in : (z == 1) ? k_in : v_in;
    const float* W   = (z == 0) ? Wq   : (z == 1) ? Wk   : Wv;
    const float* bia = (z == 0) ? bq   : (z == 1) ? bk   : bv;
    float*       C   = (z == 0) ? Cq   : (z == 1) ? Ck   : Cv;
    float        s   = (z == 0) ? qscale : 1.0f;
    gemm_body<true>(A, W, bia, C, s);
}

__global__ void __launch_bounds__(256, 1) gemm_o(
    const float* __restrict__ A, const float* __restrict__ W,
    const float* __restrict__ bias, float* __restrict__ C)
{
    gemm_body<false>(A, W, bias, C, 1.0f);
}

// ---------------- Flash attention (per (b,h,qtile=128)), tf32 mma ----------------
// Q/K/V in gmem are already tf32-rounded -> cp.async straight into smem.
// ldmatrix for Q-, K- and P-fragments; V-fragments stay scalar LDS (conflict-free).
#define ALD 132   // 128 + 4 pad
#define PLD 68    // 64 + 4 pad
#define KS_OFF (128*ALD)
#define VS_OFF (128*ALD + 64*ALD)
#define PS_OFF (128*ALD + 128*ALD)
#define ATT_SMEM_WORDS (PS_OFF + 128*PLD)
#define ATT_SMEM_BYTES (ATT_SMEM_WORDS * 4)
#define NKT (SEQ/64)

__global__ void __launch_bounds__(256, 1) attn_kernel(
    const float* __restrict__ Q, const float* __restrict__ Kp,
    const float* __restrict__ Vp, float* __restrict__ O)
{
    extern __shared__ uint32_t sm[];
    uint32_t (*Vs)[ALD] = (uint32_t(*)[ALD])(sm + VS_OFF);
    uint32_t (*Ps)[PLD] = (uint32_t(*)[PLD])(sm + PS_OFF);

    const uint32_t sbase = (uint32_t)__cvta_generic_to_shared(sm);
    const uint32_t sQ = sbase;
    const uint32_t sK = sbase + 4u * KS_OFF;
    const uint32_t sP = sbase + 4u * PS_OFF;

    const int tid  = threadIdx.x;
    const int qt = blockIdx.x, h = blockIdx.y, b = blockIdx.z;
    const int warp = tid >> 5, lane = tid & 31, g = lane >> 2, tg = lane & 3;
    const int qbase = warp * 16;

    // ldmatrix lane addressing
    const int rowAq = qbase + (lane & 7) + ((lane & 8) ? 8 : 0);   // Q/P A-frag rows
    const int colA  = (lane & 16) ? 4 : 0;
    const int rowK  = (lane & 7) + ((lane & 16) ? 8 : 0);          // K B-frag rows (+ntp*16)
    const int colK  = (lane & 8) ? 4 : 0;

    const size_t rowQ0 = (size_t)(b * SEQ + qt * 128);
    const int colH = h * HDIM;

    const int ldr = tid >> 5;       // 0..7
    const int ldc = lane * 4;       // 0..124 (words)

    // prologue: async-copy Q (128 rows), K0, V0 — one group
#pragma unroll
    for (int p = 0; p < 16; p++) {
        int rr = ldr + p * 8;
        cpa16(sbase + 4u * (rr * ALD + ldc), Q + (rowQ0 + rr) * DMODEL + colH + ldc);
    }
    {
        size_t rowK0 = (size_t)(b * SEQ);
#pragma unroll
        for (int p = 0; p < 8; p++) {
            int rr = ldr + p * 8;
            cpa16(sbase + 4u * (KS_OFF + rr * ALD + ldc), Kp + (rowK0 + rr) * DMODEL + colH + ldc);
            cpa16(sbase + 4u * (VS_OFF + rr * ALD + ldc), Vp + (rowK0 + rr) * DMODEL + colH + ldc);
        }
    }
    cpa_commit();
    cpa_wait0();
    __syncthreads();

    float acc[16][4];
#pragma unroll
    for (int nt = 0; nt < 16; nt++)
#pragma unroll
        for (int j = 0; j < 4; j++) acc[nt][j] = 0.f;

    float m0 = -1e30f, m1 = -1e30f, l0 = 0.f, l1 = 0.f;

    for (int kt = 0; kt < NKT; kt++) {
        const bool pre = (kt + 1 < NKT);
        const size_t rowKn = (size_t)(b * SEQ + (kt + 1) * 64);

        // S = Q * K^T  (M=16 per warp, N=64, K=128); 1/sqrt(dh) folded into Q
        float sf[8][4];
#pragma unroll
        for (int nt = 0; nt < 8; nt++)
#pragma unroll
            for (int j = 0; j < 4; j++) sf[nt][j] = 0.f;

#pragma unroll
        for (int ks = 0; ks < 16; ks++) {
            uint32_t a[4];
            ldsm_x4(a, sQ + 4u * (rowAq * ALD + ks * 8 + colA));
            uint32_t bfr[8][2];
#pragma unroll
            for (int ntp = 0; ntp < 4; ntp++) {
                uint32_t t[4];
                ldsm_x4(t, sK + 4u * ((rowK + ntp * 16) * ALD + ks * 8 + colK));
                bfr[2 * ntp][0] = t[0];  bfr[2 * ntp][1] = t[1];
                bfr[2 * ntp + 1][0] = t[2];  bfr[2 * ntp + 1][1] = t[3];
            }
#pragma unroll
            for (int nt = 0; nt < 8; nt++)
                mma_tf32(sf[nt], a, bfr[nt]);
        }

        // Ks free -> refill with next K tile (hidden by softmax + PV below)
        __syncthreads();
        if (pre) {
#pragma unroll
            for (int p = 0; p < 8; p++) {
                int rr = ldr + p * 8;
                cpa16(sbase + 4u * (KS_OFF + rr * ALD + ldc),
                      Kp + (rowKn + rr) * DMODEL + colH + ldc);
            }
            cpa_commit();
            cpa_wait1();   // current V tile (older group) is complete
        } else {
            cpa_wait0();
        }
        __syncthreads();

        // ---- online softmax (rows qbase+g and qbase+g+8) ----
        float tm0 = -1e30f, tm1 = -1e30f;
#pragma unroll
        for (int nt = 0; nt < 8; nt++) {
            tm0 = fmaxf(tm0, fmaxf(sf[nt][0], sf[nt][1]));
            tm1 = fmaxf(tm1, fmaxf(sf[nt][2], sf[nt][3]));
        }
        tm0 = fmaxf(tm0, __shfl_xor_sync(0xffffffffu, tm0, 1));
        tm0 = fmaxf(tm0, __shfl_xor_sync(0xffffffffu, tm0, 2));
        tm1 = fmaxf(tm1, __shfl_xor_sync(0xffffffffu, tm1, 1));
        tm1 = fmaxf(tm1, __shfl_xor_sync(0xffffffffu, tm1, 2));

        float nm0 = fmaxf(m0, tm0), nm1 = fmaxf(m1, tm1);
        float al0 = __expf(m0 - nm0), al1 = __expf(m1 - nm1);

        float ts0 = 0.f, ts1 = 0.f;
#pragma unroll
        for (int nt = 0; nt < 8; nt++) {
            sf[nt][0] = __expf(sf[nt][0] - nm0); ts0 += sf[nt][0];
            sf[nt][1] = __expf(sf[nt][1] - nm0); ts0 += sf[nt][1];
            sf[nt][2] = __expf(sf[nt][2] - nm1); ts1 += sf[nt][2];
            sf[nt][3] = __expf(sf[nt][3] - nm1); ts1 += sf[nt][3];
        }
        ts0 += __shfl_xor_sync(0xffffffffu, ts0, 1);
        ts0 += __shfl_xor_sync(0xffffffffu, ts0, 2);
        ts1 += __shfl_xor_sync(0xffffffffu, ts1, 1);
        ts1 += __shfl_xor_sync(0xffffffffu, ts1, 2);

        l0 = l0 * al0 + ts0;  l1 = l1 * al1 + ts1;
        m0 = nm0;             m1 = nm1;

#pragma unroll
        for (int nt = 0; nt < 16; nt++) {
            acc[nt][0] *= al0; acc[nt][1] *= al0;
            acc[nt][2] *= al1; acc[nt][3] *= al1;
        }

        // write P tile (warp-private rows) as tf32
#pragma unroll
        for (int nt = 0; nt < 8; nt++) {
            Ps[qbase + g][nt * 8 + 2 * tg]         = f2tf(sf[nt][0]);
            Ps[qbase + g][nt * 8 + 2 * tg + 1]     = f2tf(sf[nt][1]);
            Ps[qbase + g + 8][nt * 8 + 2 * tg]     = f2tf(sf[nt][2]);
            Ps[qbase + g + 8][nt * 8 + 2 * tg + 1] = f2tf(sf[nt][3]);
        }
        __syncwarp();

        // acc += P @ V  (M=16, N=128, K=64)
#pragma unroll
        for (int ks = 0; ks < 8; ks++) {
            uint32_t a[4];
            ldsm_x4(a, sP + 4u * (rowAq * PLD + ks * 8 + colA));
#pragma unroll
            for (int nt = 0; nt < 16; nt++) {
                uint32_t bb[2];
                bb[0] = Vs[ks * 8 + tg][nt * 8 + g];
                bb[1] = Vs[ks * 8 + tg + 4][nt * 8 + g];
                mma_tf32(acc[nt], a, bb);
            }
        }

        // Vs free -> refill with next V tile (hidden by next iteration's S-MMA)
        __syncthreads();
        if (pre) {
#pragma unroll
            for (int p = 0; p < 8; p++) {
                int rr = ldr + p * 8;
                cpa16(sbase + 4u * (VS_OFF + rr * ALD + ldc),
                      Vp + (rowKn + rr) * DMODEL + colH + ldc);
            }
            cpa_commit();
            cpa_wait1();   // next K tile (older group) is complete
        } else {
            cpa_wait0();
        }
        __syncthreads();
    }

    // epilogue: normalize, write to [B*S, D] at head column
    float inv0 = 1.f / l0, inv1 = 1.f / l1;
    size_t r0 = rowQ0 + qbase + g;
    size_t r1 = r0 + 8;
#pragma unroll
    for (int nt = 0; nt < 16; nt++) {
        int c = colH + nt * 8 + 2 * tg;
        *(float2*)&O[r0 * DMODEL + c] = make_float2(acc[nt][0] * inv0, acc[nt][1] * inv0);
        *(float2*)&O[r1 * DMODEL + c] = make_float2(acc[nt][2] * inv1, acc[nt][3] * inv1);
    }
}

// ---------------- launch ----------------
extern "C" void kernel_launch(void* const* d_in, const int* in_sizes, int n_in,
                              void* d_out, int out_size)
{
    const float* query  = (const float*)d_in[0];
    const float* key_in = (const float*)d_in[1];
    const float* value  = (const float*)d_in[2];
    const float* Wq = (const float*)d_in[3];
    const float* bq = (const float*)d_in[4];
    const float* Wk = (const float*)d_in[5];
    const float* bk = (const float*)d_in[6];
    const float* Wv = (const float*)d_in[7];
    const float* bv = (const float*)d_in[8];
    const float* Wo = (const float*)d_in[9];
    const float* bo = (const float*)d_in[10];
    float* out = (float*)d_out;

    float *gq, *gk, *gv, *ga;
    cudaGetSymbolAddress((void**)&gq, g_q);
    cudaGetSymbolAddress((void**)&gk, g_k);
    cudaGetSymbolAddress((void**)&gv, g_v);
    cudaGetSymbolAddress((void**)&ga, g_att);

    cudaFuncSetAttribute(attn_kernel,
                         cudaFuncAttributeMaxDynamicSharedMemorySize, ATT_SMEM_BYTES);
    cudaFuncSetAttribute(gemm_qkv,
                         cudaFuncAttributeMaxDynamicSharedMemorySize, GEMM_SMEM_BYTES);
    cudaFuncSetAttribute(gemm_o,
                         cudaFuncAttributeMaxDynamicSharedMemorySize, GEMM_SMEM_BYTES);

    const float qscale = 0.08838834764831845f;   // 1/sqrt(128)

    dim3 qkv_grid(DMODEL / 128, MROWS / 128, 3);   // (16, 32, 3) = 1536 CTAs
    gemm_qkv<<<qkv_grid, 256, GEMM_SMEM_BYTES>>>(query, key_in, value,
                                                 Wq, bq, Wk, bk, Wv, bv,
                                                 gq, gk, gv, qscale);

    attn_kernel<<<dim3(SEQ / 128, NHEADS, BATCH), 256, ATT_SMEM_BYTES>>>(gq, gk, gv, ga);

    gemm_o<<<dim3(DMODEL / 128, MROWS / 128), 256, GEMM_SMEM_BYTES>>>(ga, Wo, bo, out);
}

// round 12
// speedup vs baseline: 1.1712x; 1.0721x over previous
#include <cuda_runtime.h>
#include <cstdint>
#include <cstdio>

#define DMODEL 2048
#define NHEADS 16
#define HDIM   128
#define BATCH  2
#define SEQ    2048
#define MROWS  (BATCH*SEQ)   // 4096

// ---------------- scratch (device globals: allocation-free) ----------------
__device__ float g_q[(size_t)MROWS * DMODEL];
__device__ float g_k[(size_t)MROWS * DMODEL];
__device__ float g_v[(size_t)MROWS * DMODEL];
__device__ float g_att[(size_t)MROWS * DMODEL];
// tf32-rounded copies (prepass outputs)
__device__ float g_xq[(size_t)MROWS * DMODEL];
__device__ float g_xk[(size_t)MROWS * DMODEL];
__device__ float g_xv[(size_t)MROWS * DMODEL];
__device__ float g_wq[(size_t)DMODEL * DMODEL];
__device__ float g_wk[(size_t)DMODEL * DMODEL];
__device__ float g_wv[(size_t)DMODEL * DMODEL];
__device__ float g_wo[(size_t)DMODEL * DMODEL];

// ---------------- helpers ----------------
__device__ __forceinline__ uint32_t f2tf(float x) {
    uint32_t r;
    asm("cvt.rna.tf32.f32 %0, %1;" : "=r"(r) : "f"(x));
    return r;
}

__device__ __forceinline__ void mma_tf32(float* c, const uint32_t* a, const uint32_t* b) {
    asm("mma.sync.aligned.m16n8k8.row.col.f32.tf32.tf32.f32 "
        "{%0,%1,%2,%3}, {%4,%5,%6,%7}, {%8,%9}, {%0,%1,%2,%3};"
        : "+f"(c[0]), "+f"(c[1]), "+f"(c[2]), "+f"(c[3])
        : "r"(a[0]), "r"(a[1]), "r"(a[2]), "r"(a[3]),
          "r"(b[0]), "r"(b[1]));
}

__device__ __forceinline__ void ldsm_x4(uint32_t* r, uint32_t addr) {
    asm volatile("ldmatrix.sync.aligned.m8n8.x4.shared.b16 {%0,%1,%2,%3}, [%4];"
        : "=r"(r[0]), "=r"(r[1]), "=r"(r[2]), "=r"(r[3]) : "r"(addr));
}

__device__ __forceinline__ void cpa16(uint32_t dst, const void* src) {
    asm volatile("cp.async.cg.shared.global [%0], [%1], 16;" :: "r"(dst), "l"(src));
}
__device__ __forceinline__ void cpa_commit() {
    asm volatile("cp.async.commit_group;" ::: "memory");
}
__device__ __forceinline__ void cpa_wait0() {
    asm volatile("cp.async.wait_group 0;" ::: "memory");
}
__device__ __forceinline__ void cpa_wait1() {
    asm volatile("cp.async.wait_group 1;" ::: "memory");
}

// ---------------- prepass: tf32 rounding of inputs / weights ----------------
__global__ void __launch_bounds__(256) round_inputs(
    const float* __restrict__ q, const float* __restrict__ k, const float* __restrict__ v,
    float* __restrict__ oq, float* __restrict__ ok, float* __restrict__ ov)
{
    size_t idx = ((size_t)blockIdx.x * 256 + threadIdx.x) * 4;
    const float* s = (blockIdx.y == 0) ? q : (blockIdx.y == 1) ? k : v;
    float*       d = (blockIdx.y == 0) ? oq : (blockIdx.y == 1) ? ok : ov;
    float4 t = *(const float4*)(s + idx);
    uint4 u = make_uint4(f2tf(t.x), f2tf(t.y), f2tf(t.z), f2tf(t.w));
    *(uint4*)(d + idx) = u;
}

__global__ void __launch_bounds__(256) round_weights(
    const float* __restrict__ wq, const float* __restrict__ wk,
    const float* __restrict__ wv, const float* __restrict__ wo,
    float* __restrict__ oq, float* __restrict__ ok,
    float* __restrict__ ov, float* __restrict__ oo)
{
    size_t idx = ((size_t)blockIdx.x * 256 + threadIdx.x) * 4;
    const float* s = (blockIdx.y == 0) ? wq : (blockIdx.y == 1) ? wk : (blockIdx.y == 2) ? wv : wo;
    float*       d = (blockIdx.y == 0) ? oq : (blockIdx.y == 1) ? ok : (blockIdx.y == 2) ? ov : oo;
    float4 t = *(const float4*)(s + idx);
    uint4 u = make_uint4(f2tf(t.x), f2tf(t.y), f2tf(t.z), f2tf(t.w));
    *(uint4*)(d + idx) = u;
}

// ---------------- GEMM body: C = (A @ W^T + bias) * scale ----------------
// A and W already tf32-rounded in gmem. cp.async double-buffered mainloop,
// ldmatrix fragment loads, 2 CTAs/SM.
#define GT_K 32
#define GLD  36                 // 32 + 4 pad (stride%32==4 -> conflict-free)
#define GSTG (128*GLD)          // words per matrix per stage
#define GEMM_SMEM_BYTES (4*GSTG*4)   // 73728 B -> 2 CTAs/SM fits

template<bool ROUND>
__device__ __forceinline__ void gemm_body(
    const float* __restrict__ A, const float* __restrict__ W,
    const float* __restrict__ bias, float* __restrict__ C, float scale)
{
    extern __shared__ uint32_t gsm[];
    const uint32_t sbase = (uint32_t)__cvta_generic_to_shared(gsm);

    const int tid  = threadIdx.x;
    const int ctaN = blockIdx.x * 128;
    const int ctaM = blockIdx.y * 128;

    const int warp = tid >> 5, lane = tid & 31;
    const int g = lane >> 2, tg = lane & 3;
    const int wm = (warp & 1) * 64;
    const int wn = (warp >> 1) * 32;

    const int rowA = wm + (lane & 7) + ((lane & 8) ? 8 : 0);
    const int colA = (lane & 16) ? 4 : 0;
    const int rowB = wn + (lane & 7) + ((lane & 16) ? 8 : 0);
    const int colB = (lane & 8) ? 4 : 0;

    const int lr = tid >> 3;        // 0..31
    const int lc = (tid & 7) * 4;   // 0..28

    const float* Abase = A + (size_t)(ctaM + lr) * DMODEL + lc;
    const float* Wbase = W + (size_t)(ctaN + lr) * DMODEL + lc;

    float acc[4][4][4];
#pragma unroll
    for (int mt = 0; mt < 4; mt++)
#pragma unroll
        for (int nt = 0; nt < 4; nt++)
#pragma unroll
            for (int j = 0; j < 4; j++) acc[mt][nt][j] = 0.f;

    const int nk = DMODEL / GT_K;

    // async-copy k-tile kt into stage s
    auto issue = [&](int kt, int s) {
        const float* An = Abase + (size_t)kt * GT_K;
        const float* Wn = Wbase + (size_t)kt * GT_K;
        uint32_t dA = sbase + 4u * ((uint32_t)(s * 2 * GSTG) + lr * GLD + lc);
        uint32_t dW = dA + 4u * (uint32_t)GSTG;
#pragma unroll
        for (int p = 0; p < 4; p++) {
            cpa16(dA + 4u * (p * 32 * GLD), An + (size_t)(p * 32) * DMODEL);
            cpa16(dW + 4u * (p * 32 * GLD), Wn + (size_t)(p * 32) * DMODEL);
        }
        cpa_commit();
    };

    issue(0, 0);
    cpa_wait0();
    __syncthreads();

    for (int kt = 0; kt < nk; kt++) {
        const int cur = kt & 1;
        const bool pre = (kt + 1 < nk);
        if (pre) issue(kt + 1, cur ^ 1);

        const uint32_t sA = sbase + (uint32_t)(cur * 2 * GSTG) * 4u;
        const uint32_t sW = sA + (uint32_t)GSTG * 4u;

#pragma unroll
        for (int ks = 0; ks < 4; ks++) {
            uint32_t a[4][4];
#pragma unroll
            for (int mt = 0; mt < 4; mt++)
                ldsm_x4(a[mt], sA + 4u * ((rowA + mt * 16) * GLD + ks * 8 + colA));
            uint32_t bfr[4][2];
#pragma unroll
            for (int ntp = 0; ntp < 2; ntp++) {
                uint32_t t[4];
                ldsm_x4(t, sW + 4u * ((rowB + ntp * 16) * GLD + ks * 8 + colB));
                bfr[2 * ntp][0] = t[0];  bfr[2 * ntp][1] = t[1];
                bfr[2 * ntp + 1][0] = t[2];  bfr[2 * ntp + 1][1] = t[3];
            }
#pragma unroll
            for (int mt = 0; mt < 4; mt++)
#pragma unroll
                for (int nt = 0; nt < 4; nt++)
                    mma_tf32(acc[mt][nt], a[mt], bfr[nt]);
        }

        if (pre) cpa_wait0();
        __syncthreads();
    }

    // epilogue: bias + scale; optionally round outputs to tf32 (for q/k/v scratch)
#pragma unroll
    for (int mt = 0; mt < 4; mt++) {
        int r0 = ctaM + wm + mt * 16 + g;
        int r1 = r0 + 8;
#pragma unroll
        for (int nt = 0; nt < 4; nt++) {
            int c = ctaN + wn + nt * 8 + 2 * tg;
            float b0 = bias[c], b1 = bias[c + 1];
            float v00 = (acc[mt][nt][0] + b0) * scale;
            float v01 = (acc[mt][nt][1] + b1) * scale;
            float v10 = (acc[mt][nt][2] + b0) * scale;
            float v11 = (acc[mt][nt][3] + b1) * scale;
            if (ROUND) {
                v00 = __uint_as_float(f2tf(v00));
                v01 = __uint_as_float(f2tf(v01));
                v10 = __uint_as_float(f2tf(v10));
                v11 = __uint_as_float(f2tf(v11));
            }
            *(float2*)&C[(size_t)r0 * DMODEL + c] = make_float2(v00, v01);
            *(float2*)&C[(size_t)r1 * DMODEL + c] = make_float2(v10, v11);
        }
    }
}

// Fused Q/K/V projections (inputs pre-rounded). Outputs tf32-rounded.
__global__ void __launch_bounds__(256, 2) gemm_qkv(
    const float* __restrict__ q_in, const float* __restrict__ k_in, const float* __restrict__ v_in,
    const float* __restrict__ Wq, const float* __restrict__ bq,
    const float* __restrict__ Wk, const float* __restrict__ bk,
    const float* __restrict__ Wv, const float* __restrict__ bv,
    float* __restrict__ Cq, float* __restrict__ Ck, float* __restrict__ Cv,
    float qscale)
{
    const int z = blockIdx.z;
    const float* A   = (z == 0) ? q_in : (z == 1) ? k_in : v_in;
    const float* W   = (z == 0) ? Wq   : (z == 1) ? Wk   : Wv;
    const float* bia = (z == 0) ? bq   : (z == 1) ? bk   : bv;
    float*       C   = (z == 0) ? Cq   : (z == 1) ? Ck   : Cv;
    float        s   = (z == 0) ? qscale : 1.0f;
    gemm_body<true>(A, W, bia, C, s);
}

__global__ void __launch_bounds__(256, 2) gemm_o(
    const float* __restrict__ A, const float* __restrict__ W,
    const float* __restrict__ bias, float* __restrict__ C)
{
    gemm_body<false>(A, W, bias, C, 1.0f);
}

// ---------------- Flash attention (per (b,h,qtile=128)), tf32 mma ----------------
// Q/K/V in gmem are already tf32-rounded -> cp.async straight into smem.
// ldmatrix for Q-, K- and P-fragments; V-fragments scalar LDS (conflict-free).
// Output rounded to tf32 (consumed by gemm_o's raw cp.async path).
#define ALD 132   // 128 + 4 pad
#define PLD 68    // 64 + 4 pad
#define KS_OFF (128*ALD)
#define VS_OFF (128*ALD + 64*ALD)
#define PS_OFF (128*ALD + 128*ALD)
#define ATT_SMEM_WORDS (PS_OFF + 128*PLD)
#define ATT_SMEM_BYTES (ATT_SMEM_WORDS * 4)
#define NKT (SEQ/64)

__global__ void __launch_bounds__(256, 1) attn_kernel(
    const float* __restrict__ Q, const float* __restrict__ Kp,
    const float* __restrict__ Vp, float* __restrict__ O)
{
    extern __shared__ uint32_t sm[];
    uint32_t (*Vs)[ALD] = (uint32_t(*)[ALD])(sm + VS_OFF);
    uint32_t (*Ps)[PLD] = (uint32_t(*)[PLD])(sm + PS_OFF);

    const uint32_t sbase = (uint32_t)__cvta_generic_to_shared(sm);
    const uint32_t sQ = sbase;
    const uint32_t sK = sbase + 4u * KS_OFF;
    const uint32_t sP = sbase + 4u * PS_OFF;

    const int tid  = threadIdx.x;
    const int qt = blockIdx.x, h = blockIdx.y, b = blockIdx.z;
    const int warp = tid >> 5, lane = tid & 31, g = lane >> 2, tg = lane & 3;
    const int qbase = warp * 16;

    const int rowAq = qbase + (lane & 7) + ((lane & 8) ? 8 : 0);
    const int colA  = (lane & 16) ? 4 : 0;
    const int rowK  = (lane & 7) + ((lane & 16) ? 8 : 0);
    const int colK  = (lane & 8) ? 4 : 0;

    const size_t rowQ0 = (size_t)(b * SEQ + qt * 128);
    const int colH = h * HDIM;

    const int ldr = tid >> 5;       // 0..7
    const int ldc = lane * 4;       // 0..124 (words)

    // prologue: async-copy Q (128 rows), K0, V0 — one group
#pragma unroll
    for (int p = 0; p < 16; p++) {
        int rr = ldr + p * 8;
        cpa16(sbase + 4u * (rr * ALD + ldc), Q + (rowQ0 + rr) * DMODEL + colH + ldc);
    }
    {
        size_t rowK0 = (size_t)(b * SEQ);
#pragma unroll
        for (int p = 0; p < 8; p++) {
            int rr = ldr + p * 8;
            cpa16(sbase + 4u * (KS_OFF + rr * ALD + ldc), Kp + (rowK0 + rr) * DMODEL + colH + ldc);
            cpa16(sbase + 4u * (VS_OFF + rr * ALD + ldc), Vp + (rowK0 + rr) * DMODEL + colH + ldc);
        }
    }
    cpa_commit();
    cpa_wait0();
    __syncthreads();

    float acc[16][4];
#pragma unroll
    for (int nt = 0; nt < 16; nt++)
#pragma unroll
        for (int j = 0; j < 4; j++) acc[nt][j] = 0.f;

    float m0 = -1e30f, m1 = -1e30f, l0 = 0.f, l1 = 0.f;

    for (int kt = 0; kt < NKT; kt++) {
        const bool pre = (kt + 1 < NKT);
        const size_t rowKn = (size_t)(b * SEQ + (kt + 1) * 64);

        // S = Q * K^T  (M=16 per warp, N=64, K=128); 1/sqrt(dh) folded into Q
        float sf[8][4];
#pragma unroll
        for (int nt = 0; nt < 8; nt++)
#pragma unroll
            for (int j = 0; j < 4; j++) sf[nt][j] = 0.f;

#pragma unroll
        for (int ks = 0; ks < 16; ks++) {
            uint32_t a[4];
            ldsm_x4(a, sQ + 4u * (rowAq * ALD + ks * 8 + colA));
            uint32_t bfr[8][2];
#pragma unroll
            for (int ntp = 0; ntp < 4; ntp++) {
                uint32_t t[4];
                ldsm_x4(t, sK + 4u * ((rowK + ntp * 16) * ALD + ks * 8 + colK));
                bfr[2 * ntp][0] = t[0];  bfr[2 * ntp][1] = t[1];
                bfr[2 * ntp + 1][0] = t[2];  bfr[2 * ntp + 1][1] = t[3];
            }
#pragma unroll
            for (int nt = 0; nt < 8; nt++)
                mma_tf32(sf[nt], a, bfr[nt]);
        }

        // Ks free -> refill with next K tile (hidden by softmax + PV below)
        __syncthreads();
        if (pre) {
#pragma unroll
            for (int p = 0; p < 8; p++) {
                int rr = ldr + p * 8;
                cpa16(sbase + 4u * (KS_OFF + rr * ALD + ldc),
                      Kp + (rowKn + rr) * DMODEL + colH + ldc);
            }
            cpa_commit();
            cpa_wait1();   // current V tile (older group) is complete
        } else {
            cpa_wait0();
        }
        __syncthreads();

        // ---- online softmax (rows qbase+g and qbase+g+8) ----
        float tm0 = -1e30f, tm1 = -1e30f;
#pragma unroll
        for (int nt = 0; nt < 8; nt++) {
            tm0 = fmaxf(tm0, fmaxf(sf[nt][0], sf[nt][1]));
            tm1 = fmaxf(tm1, fmaxf(sf[nt][2], sf[nt][3]));
        }
        tm0 = fmaxf(tm0, __shfl_xor_sync(0xffffffffu, tm0, 1));
        tm0 = fmaxf(tm0, __shfl_xor_sync(0xffffffffu, tm0, 2));
        tm1 = fmaxf(tm1, __shfl_xor_sync(0xffffffffu, tm1, 1));
        tm1 = fmaxf(tm1, __shfl_xor_sync(0xffffffffu, tm1, 2));

        float nm0 = fmaxf(m0, tm0), nm1 = fmaxf(m1, tm1);
        float al0 = __expf(m0 - nm0), al1 = __expf(m1 - nm1);

        float ts0 = 0.f, ts1 = 0.f;
#pragma unroll
        for (int nt = 0; nt < 8; nt++) {
            sf[nt][0] = __expf(sf[nt][0] - nm0); ts0 += sf[nt][0];
            sf[nt][1] = __expf(sf[nt][1] - nm0); ts0 += sf[nt][1];
            sf[nt][2] = __expf(sf[nt][2] - nm1); ts1 += sf[nt][2];
            sf[nt][3] = __expf(sf[nt][3] - nm1); ts1 += sf[nt][3];
        }
        ts0 += __shfl_xor_sync(0xffffffffu, ts0, 1);
        ts0 += __shfl_xor_sync(0xffffffffu, ts0, 2);
        ts1 += __shfl_xor_sync(0xffffffffu, ts1, 1);
        ts1 += __shfl_xor_sync(0xffffffffu, ts1, 2);

        l0 = l0 * al0 + ts0;  l1 = l1 * al1 + ts1;
        m0 = nm0;             m1 = nm1;

#pragma unroll
        for (int nt = 0; nt < 16; nt++) {
            acc[nt][0] *= al0; acc[nt][1] *= al0;
            acc[nt][2] *= al1; acc[nt][3] *= al1;
        }

        // write P tile (warp-private rows) as tf32
#pragma unroll
        for (int nt = 0; nt < 8; nt++) {
            Ps[qbase + g][nt * 8 + 2 * tg]         = f2tf(sf[nt][0]);
            Ps[qbase + g][nt * 8 + 2 * tg + 1]     = f2tf(sf[nt][1]);
            Ps[qbase + g + 8][nt * 8 + 2 * tg]     = f2tf(sf[nt][2]);
            Ps[qbase + g + 8][nt * 8 + 2 * tg + 1] = f2tf(sf[nt][3]);
        }
        __syncwarp();

        // acc += P @ V  (M=16, N=128, K=64)
#pragma unroll
        for (int ks = 0; ks < 8; ks++) {
            uint32_t a[4];
            ldsm_x4(a, sP + 4u * (rowAq * PLD + ks * 8 + colA));
#pragma unroll
            for (int nt = 0; nt < 16; nt++) {
                uint32_t bb[2];
                bb[0] = Vs[ks * 8 + tg][nt * 8 + g];
                bb[1] = Vs[ks * 8 + tg + 4][nt * 8 + g];
                mma_tf32(acc[nt], a, bb);
            }
        }

        // Vs free -> refill with next V tile (hidden by next iteration's S-MMA)
        __syncthreads();
        if (pre) {
#pragma unroll
            for (int p = 0; p < 8; p++) {
                int rr = ldr + p * 8;
                cpa16(sbase + 4u * (VS_OFF + rr * ALD + ldc),
                      Vp + (rowKn + rr) * DMODEL + colH + ldc);
            }
            cpa_commit();
            cpa_wait1();   // next K tile (older group) is complete
        } else {
            cpa_wait0();
        }
        __syncthreads();
    }

    // epilogue: normalize, round to tf32 (gemm_o consumes raw), write out
    float inv0 = 1.f / l0, inv1 = 1.f / l1;
    size_t r0 = rowQ0 + qbase + g;
    size_t r1 = r0 + 8;
#pragma unroll
    for (int nt = 0; nt < 16; nt++) {
        int c = colH + nt * 8 + 2 * tg;
        float2 w0 = make_float2(__uint_as_float(f2tf(acc[nt][0] * inv0)),
                                __uint_as_float(f2tf(acc[nt][1] * inv0)));
        float2 w1 = make_float2(__uint_as_float(f2tf(acc[nt][2] * inv1)),
                                __uint_as_float(f2tf(acc[nt][3] * inv1)));
        *(float2*)&O[r0 * DMODEL + c] = w0;
        *(float2*)&O[r1 * DMODEL + c] = w1;
    }
}

// ---------------- launch ----------------
extern "C" void kernel_launch(void* const* d_in, const int* in_sizes, int n_in,
                              void* d_out, int out_size)
{
    const float* query  = (const float*)d_in[0];
    const float* key_in = (const float*)d_in[1];
    const float* value  = (const float*)d_in[2];
    const float* Wq = (const float*)d_in[3];
    const float* bq = (const float*)d_in[4];
    const float* Wk = (const float*)d_in[5];
    const float* bk = (const float*)d_in[6];
    const float* Wv = (const float*)d_in[7];
    const float* bv = (const float*)d_in[8];
    const float* Wo = (const float*)d_in[9];
    const float* bo = (const float*)d_in[10];
    float* out = (float*)d_out;

    float *gq, *gk, *gv, *ga;
    float *xq, *xk, *xv, *wq, *wk, *wv, *wo;
    cudaGetSymbolAddress((void**)&gq, g_q);
    cudaGetSymbolAddress((void**)&gk, g_k);
    cudaGetSymbolAddress((void**)&gv, g_v);
    cudaGetSymbolAddress((void**)&ga, g_att);
    cudaGetSymbolAddress((void**)&xq, g_xq);
    cudaGetSymbolAddress((void**)&xk, g_xk);
    cudaGetSymbolAddress((void**)&xv, g_xv);
    cudaGetSymbolAddress((void**)&wq, g_wq);
    cudaGetSymbolAddress((void**)&wk, g_wk);
    cudaGetSymbolAddress((void**)&wv, g_wv);
    cudaGetSymbolAddress((void**)&wo, g_wo);

    cudaFuncSetAttribute(attn_kernel,
                         cudaFuncAttributeMaxDynamicSharedMemorySize, ATT_SMEM_BYTES);
    cudaFuncSetAttribute(gemm_qkv,
                         cudaFuncAttributeMaxDynamicSharedMemorySize, GEMM_SMEM_BYTES);
    cudaFuncSetAttribute(gemm_o,
                         cudaFuncAttributeMaxDynamicSharedMemorySize, GEMM_SMEM_BYTES);

    const float qscale = 0.08838834764831845f;   // 1/sqrt(128)

    // prepass: tf32-round inputs + weights
    {
        dim3 gi((MROWS * DMODEL) / (4 * 256), 3);    // (8192, 3)
        round_inputs<<<gi, 256>>>(query, key_in, value, xq, xk, xv);
        dim3 gw((DMODEL * DMODEL) / (4 * 256), 4);   // (4096, 4)
        round_weights<<<gw, 256>>>(Wq, Wk, Wv, Wo, wq, wk, wv, wo);
    }

    dim3 qkv_grid(DMODEL / 128, MROWS / 128, 3);   // (16, 32, 3) = 1536 CTAs
    gemm_qkv<<<qkv_grid, 256, GEMM_SMEM_BYTES>>>(xq, xk, xv,
                                                 wq, bq, wk, bk, wv, bv,
                                                 gq, gk, gv, qscale);

    attn_kernel<<<dim3(SEQ / 128, NHEADS, BATCH), 256, ATT_SMEM_BYTES>>>(gq, gk, gv, ga);

    gemm_o<<<dim3(DMODEL / 128, MROWS / 128), 256, GEMM_SMEM_BYTES>>>(ga, wo, bo, out);
}

// round 13
// speedup vs baseline: 1.1939x; 1.0194x over previous
#include <cuda_runtime.h>
#include <cstdint>
#include <cstdio>

#define DMODEL 2048
#define NHEADS 16
#define HDIM   128
#define BATCH  2
#define SEQ    2048
#define MROWS  (BATCH*SEQ)   // 4096

// ---------------- scratch (device globals: allocation-free) ----------------
__device__ float g_q[(size_t)MROWS * DMODEL];
__device__ float g_k[(size_t)MROWS * DMODEL];
__device__ float g_v[(size_t)MROWS * DMODEL];
__device__ float g_att[(size_t)MROWS * DMODEL];
// tf32-rounded copies (prepass outputs)
__device__ float g_xq[(size_t)MROWS * DMODEL];
__device__ float g_xk[(size_t)MROWS * DMODEL];
__device__ float g_xv[(size_t)MROWS * DMODEL];
__device__ float g_wq[(size_t)DMODEL * DMODEL];
__device__ float g_wk[(size_t)DMODEL * DMODEL];
__device__ float g_wv[(size_t)DMODEL * DMODEL];
__device__ float g_wo[(size_t)DMODEL * DMODEL];

// ---------------- helpers ----------------
__device__ __forceinline__ uint32_t f2tf(float x) {
    uint32_t r;
    asm("cvt.rna.tf32.f32 %0, %1;" : "=r"(r) : "f"(x));
    return r;
}

__device__ __forceinline__ void mma_tf32(float* c, const uint32_t* a, const uint32_t* b) {
    asm("mma.sync.aligned.m16n8k8.row.col.f32.tf32.tf32.f32 "
        "{%0,%1,%2,%3}, {%4,%5,%6,%7}, {%8,%9}, {%0,%1,%2,%3};"
        : "+f"(c[0]), "+f"(c[1]), "+f"(c[2]), "+f"(c[3])
        : "r"(a[0]), "r"(a[1]), "r"(a[2]), "r"(a[3]),
          "r"(b[0]), "r"(b[1]));
}

__device__ __forceinline__ void ldsm_x4(uint32_t* r, uint32_t addr) {
    asm volatile("ldmatrix.sync.aligned.m8n8.x4.shared.b16 {%0,%1,%2,%3}, [%4];"
        : "=r"(r[0]), "=r"(r[1]), "=r"(r[2]), "=r"(r[3]) : "r"(addr));
}

__device__ __forceinline__ void cpa16(uint32_t dst, const void* src) {
    asm volatile("cp.async.cg.shared.global [%0], [%1], 16;" :: "r"(dst), "l"(src));
}
__device__ __forceinline__ void cpa_commit() {
    asm volatile("cp.async.commit_group;" ::: "memory");
}
__device__ __forceinline__ void cpa_wait0() {
    asm volatile("cp.async.wait_group 0;" ::: "memory");
}
__device__ __forceinline__ void cpa_wait1() {
    asm volatile("cp.async.wait_group 1;" ::: "memory");
}
__device__ __forceinline__ void cpa_wait2() {
    asm volatile("cp.async.wait_group 2;" ::: "memory");
}

// ---------------- prepass: tf32 rounding of inputs / weights ----------------
__global__ void __launch_bounds__(256) round_inputs(
    const float* __restrict__ q, const float* __restrict__ k, const float* __restrict__ v,
    float* __restrict__ oq, float* __restrict__ ok, float* __restrict__ ov)
{
    size_t idx = ((size_t)blockIdx.x * 256 + threadIdx.x) * 4;
    const float* s = (blockIdx.y == 0) ? q : (blockIdx.y == 1) ? k : v;
    float*       d = (blockIdx.y == 0) ? oq : (blockIdx.y == 1) ? ok : ov;
    float4 t = *(const float4*)(s + idx);
    uint4 u = make_uint4(f2tf(t.x), f2tf(t.y), f2tf(t.z), f2tf(t.w));
    *(uint4*)(d + idx) = u;
}

__global__ void __launch_bounds__(256) round_weights(
    const float* __restrict__ wq, const float* __restrict__ wk,
    const float* __restrict__ wv, const float* __restrict__ wo,
    float* __restrict__ oq, float* __restrict__ ok,
    float* __restrict__ ov, float* __restrict__ oo)
{
    size_t idx = ((size_t)blockIdx.x * 256 + threadIdx.x) * 4;
    const float* s = (blockIdx.y == 0) ? wq : (blockIdx.y == 1) ? wk : (blockIdx.y == 2) ? wv : wo;
    float*       d = (blockIdx.y == 0) ? oq : (blockIdx.y == 1) ? ok : (blockIdx.y == 2) ? ov : oo;
    float4 t = *(const float4*)(s + idx);
    uint4 u = make_uint4(f2tf(t.x), f2tf(t.y), f2tf(t.z), f2tf(t.w));
    *(uint4*)(d + idx) = u;
}

// ---------------- GEMM body: C = (A @ W^T + bias) * scale ----------------
#define GT_K 32
#define GLD  36
#define GSTG (128*GLD)
#define GEMM_SMEM_BYTES (4*GSTG*4)   // 73728 B -> 2 CTAs/SM

template<bool ROUND>
__device__ __forceinline__ void gemm_body(
    const float* __restrict__ A, const float* __restrict__ W,
    const float* __restrict__ bias, float* __restrict__ C, float scale)
{
    extern __shared__ uint32_t gsm[];
    const uint32_t sbase = (uint32_t)__cvta_generic_to_shared(gsm);

    const int tid  = threadIdx.x;
    const int ctaN = blockIdx.x * 128;
    const int ctaM = blockIdx.y * 128;

    const int warp = tid >> 5, lane = tid & 31;
    const int g = lane >> 2, tg = lane & 3;
    const int wm = (warp & 1) * 64;
    const int wn = (warp >> 1) * 32;

    const int rowA = wm + (lane & 7) + ((lane & 8) ? 8 : 0);
    const int colA = (lane & 16) ? 4 : 0;
    const int rowB = wn + (lane & 7) + ((lane & 16) ? 8 : 0);
    const int colB = (lane & 8) ? 4 : 0;

    const int lr = tid >> 3;
    const int lc = (tid & 7) * 4;

    const float* Abase = A + (size_t)(ctaM + lr) * DMODEL + lc;
    const float* Wbase = W + (size_t)(ctaN + lr) * DMODEL + lc;

    float acc[4][4][4];
#pragma unroll
    for (int mt = 0; mt < 4; mt++)
#pragma unroll
        for (int nt = 0; nt < 4; nt++)
#pragma unroll
            for (int j = 0; j < 4; j++) acc[mt][nt][j] = 0.f;

    const int nk = DMODEL / GT_K;

    auto issue = [&](int kt, int s) {
        const float* An = Abase + (size_t)kt * GT_K;
        const float* Wn = Wbase + (size_t)kt * GT_K;
        uint32_t dA = sbase + 4u * ((uint32_t)(s * 2 * GSTG) + lr * GLD + lc);
        uint32_t dW = dA + 4u * (uint32_t)GSTG;
#pragma unroll
        for (int p = 0; p < 4; p++) {
            cpa16(dA + 4u * (p * 32 * GLD), An + (size_t)(p * 32) * DMODEL);
            cpa16(dW + 4u * (p * 32 * GLD), Wn + (size_t)(p * 32) * DMODEL);
        }
        cpa_commit();
    };

    issue(0, 0);
    cpa_wait0();
    __syncthreads();

    for (int kt = 0; kt < nk; kt++) {
        const int cur = kt & 1;
        const bool pre = (kt + 1 < nk);
        if (pre) issue(kt + 1, cur ^ 1);

        const uint32_t sA = sbase + (uint32_t)(cur * 2 * GSTG) * 4u;
        const uint32_t sW = sA + (uint32_t)GSTG * 4u;

#pragma unroll
        for (int ks = 0; ks < 4; ks++) {
            uint32_t a[4][4];
#pragma unroll
            for (int mt = 0; mt < 4; mt++)
                ldsm_x4(a[mt], sA + 4u * ((rowA + mt * 16) * GLD + ks * 8 + colA));
            uint32_t bfr[4][2];
#pragma unroll
            for (int ntp = 0; ntp < 2; ntp++) {
                uint32_t t[4];
                ldsm_x4(t, sW + 4u * ((rowB + ntp * 16) * GLD + ks * 8 + colB));
                bfr[2 * ntp][0] = t[0];  bfr[2 * ntp][1] = t[1];
                bfr[2 * ntp + 1][0] = t[2];  bfr[2 * ntp + 1][1] = t[3];
            }
#pragma unroll
            for (int mt = 0; mt < 4; mt++)
#pragma unroll
                for (int nt = 0; nt < 4; nt++)
                    mma_tf32(acc[mt][nt], a[mt], bfr[nt]);
        }

        if (pre) cpa_wait0();
        __syncthreads();
    }

#pragma unroll
    for (int mt = 0; mt < 4; mt++) {
        int r0 = ctaM + wm + mt * 16 + g;
        int r1 = r0 + 8;
#pragma unroll
        for (int nt = 0; nt < 4; nt++) {
            int c = ctaN + wn + nt * 8 + 2 * tg;
            float b0 = bias[c], b1 = bias[c + 1];
            float v00 = (acc[mt][nt][0] + b0) * scale;
            float v01 = (acc[mt][nt][1] + b1) * scale;
            float v10 = (acc[mt][nt][2] + b0) * scale;
            float v11 = (acc[mt][nt][3] + b1) * scale;
            if (ROUND) {
                v00 = __uint_as_float(f2tf(v00));
                v01 = __uint_as_float(f2tf(v01));
                v10 = __uint_as_float(f2tf(v10));
                v11 = __uint_as_float(f2tf(v11));
            }
            *(float2*)&C[(size_t)r0 * DMODEL + c] = make_float2(v00, v01);
            *(float2*)&C[(size_t)r1 * DMODEL + c] = make_float2(v10, v11);
        }
    }
}

__global__ void __launch_bounds__(256, 2) gemm_qkv(
    const float* __restrict__ q_in, const float* __restrict__ k_in, const float* __restrict__ v_in,
    const float* __restrict__ Wq, const float* __restrict__ bq,
    const float* __restrict__ Wk, const float* __restrict__ bk,
    const float* __restrict__ Wv, const float* __restrict__ bv,
    float* __restrict__ Cq, float* __restrict__ Ck, float* __restrict__ Cv,
    float qscale)
{
    const int z = blockIdx.z;
    const float* A   = (z == 0) ? q_in : (z == 1) ? k_in : v_in;
    const float* W   = (z == 0) ? Wq   : (z == 1) ? Wk   : Wv;
    const float* bia = (z == 0) ? bq   : (z == 1) ? bk   : bv;
    float*       C   = (z == 0) ? Cq   : (z == 1) ? Ck   : Cv;
    float        s   = (z == 0) ? qscale : 1.0f;
    gemm_body<true>(A, W, bia, C, s);
}

__global__ void __launch_bounds__(256, 2) gemm_o(
    const float* __restrict__ A, const float* __restrict__ W,
    const float* __restrict__ bias, float* __restrict__ C)
{
    gemm_body<false>(A, W, bias, C, 1.0f);
}

// ---------------- Flash attention, cross-iteration S-prefetch ----------------
// K double-buffered; two score fragments (sfA/sfB). Each iter: issue S(kt+1)
// MMAs first, then softmax(kt) overlaps the HMMA drain, then PV(kt).
// cp.async groups: iter kt commits A_kt=K(kt+2) at top, B_kt=V(kt+1) at bottom
// (empty groups at the tail keep wait counts uniform).
#define ALD 132   // 128 + 4 pad
#define PLD 68    // 64 + 4 pad
#define K0_OFF (128*ALD)
#define K1_OFF (128*ALD + 64*ALD)
#define VV_OFF (128*ALD + 2*64*ALD)
#define PP_OFF (128*ALD + 3*64*ALD)
#define ATT_SMEM_WORDS (PP_OFF + 128*PLD)
#define ATT_SMEM_BYTES (ATT_SMEM_WORDS * 4)   // 203776 B
#define NKT (SEQ/64)

__global__ void __launch_bounds__(256, 1) attn_kernel(
    const float* __restrict__ Q, const float* __restrict__ Kp,
    const float* __restrict__ Vp, float* __restrict__ O)
{
    extern __shared__ uint32_t sm[];
    uint32_t (*Vs)[ALD] = (uint32_t(*)[ALD])(sm + VV_OFF);
    uint32_t (*Ps)[PLD] = (uint32_t(*)[PLD])(sm + PP_OFF);

    const uint32_t sbase = (uint32_t)__cvta_generic_to_shared(sm);
    const uint32_t sQ  = sbase;
    const uint32_t sK0 = sbase + 4u * K0_OFF;
    const uint32_t sK1 = sbase + 4u * K1_OFF;
    const uint32_t sVb = sbase + 4u * VV_OFF;
    const uint32_t sP  = sbase + 4u * PP_OFF;

    const int tid  = threadIdx.x;
    const int qt = blockIdx.x, h = blockIdx.y, b = blockIdx.z;
    const int warp = tid >> 5, lane = tid & 31, g = lane >> 2, tg = lane & 3;
    const int qbase = warp * 16;

    const int rowAq = qbase + (lane & 7) + ((lane & 8) ? 8 : 0);
    const int colA  = (lane & 16) ? 4 : 0;
    const int rowK  = (lane & 7) + ((lane & 16) ? 8 : 0);
    const int colK  = (lane & 8) ? 4 : 0;

    const size_t rowQ0 = (size_t)(b * SEQ + qt * 128);
    const int colH = h * HDIM;

    const int ldr = tid >> 5;       // 0..7
    const int ldc = lane * 4;       // 0..124 (words)

    // prologue: G1 = {Q, K(0), V(0)}, G2 = {K(1)}, then drain all
#pragma unroll
    for (int p = 0; p < 16; p++) {
        int rr = ldr + p * 8;
        cpa16(sQ + 4u * (rr * ALD + ldc), Q + (rowQ0 + rr) * DMODEL + colH + ldc);
    }
    {
        size_t rowK0 = (size_t)(b * SEQ);
#pragma unroll
        for (int p = 0; p < 8; p++) {
            int rr = ldr + p * 8;
            cpa16(sK0 + 4u * (rr * ALD + ldc), Kp + (rowK0 + rr) * DMODEL + colH + ldc);
            cpa16(sVb + 4u * (rr * ALD + ldc), Vp + (rowK0 + rr) * DMODEL + colH + ldc);
        }
        cpa_commit();
#pragma unroll
        for (int p = 0; p < 8; p++) {
            int rr = ldr + p * 8;
            cpa16(sK1 + 4u * (rr * ALD + ldc), Kp + (rowK0 + 64 + rr) * DMODEL + colH + ldc);
        }
        cpa_commit();
    }
    cpa_wait0();
    __syncthreads();

    float acc[16][4];
#pragma unroll
    for (int nt = 0; nt < 16; nt++)
#pragma unroll
        for (int j = 0; j < 4; j++) acc[nt][j] = 0.f;

    float m0 = -1e30f, m1 = -1e30f, l0 = 0.f, l1 = 0.f;

    float sfA[8][4], sfB[8][4];

    // S = Q * K^T into sf (M=16/warp, N=64, K=128); 1/sqrt(dh) folded into Q
    auto smma = [&](float (*sf)[4], uint32_t sKb) {
#pragma unroll
        for (int nt = 0; nt < 8; nt++)
#pragma unroll
            for (int j = 0; j < 4; j++) sf[nt][j] = 0.f;
#pragma unroll
        for (int ks = 0; ks < 16; ks++) {
            uint32_t a[4];
            ldsm_x4(a, sQ + 4u * (rowAq * ALD + ks * 8 + colA));
            uint32_t bfr[8][2];
#pragma unroll
            for (int ntp = 0; ntp < 4; ntp++) {
                uint32_t t[4];
                ldsm_x4(t, sKb + 4u * ((rowK + ntp * 16) * ALD + ks * 8 + colK));
                bfr[2 * ntp][0] = t[0];  bfr[2 * ntp][1] = t[1];
                bfr[2 * ntp + 1][0] = t[2];  bfr[2 * ntp + 1][1] = t[3];
            }
#pragma unroll
            for (int nt = 0; nt < 8; nt++)
                mma_tf32(sf[nt], a, bfr[nt]);
        }
    };

    smma(sfA, sK0);   // S(0)

    auto step = [&](int kt, float (*sfC)[4], float (*sfN)[4],
                    uint32_t sKnext, uint32_t dKrefill) {
        __syncthreads();                                  // bar_a: K-buf + iteration join
        // commit A_kt = K(kt+2) -> dKrefill (empty group if out of range)
        if (kt + 2 < NKT) {
            size_t rowK2 = (size_t)(b * SEQ + (kt + 2) * 64);
#pragma unroll
            for (int p = 0; p < 8; p++) {
                int rr = ldr + p * 8;
                cpa16(dKrefill + 4u * (rr * ALD + ldc),
                      Kp + (rowK2 + rr) * DMODEL + colH + ldc);
            }
        }
        cpa_commit();
        cpa_wait2();                                      // drain A_{kt-1} = K(kt+1)
        __syncthreads();                                  // bar_b: K(kt+1) visible

        if (kt + 1 < NKT) smma(sfN, sKnext);              // issue next S (overlaps softmax)

        // ---- online softmax on sfC ----
        float tm0 = -1e30f, tm1 = -1e30f;
#pragma unroll
        for (int nt = 0; nt < 8; nt++) {
            tm0 = fmaxf(tm0, fmaxf(sfC[nt][0], sfC[nt][1]));
            tm1 = fmaxf(tm1, fmaxf(sfC[nt][2], sfC[nt][3]));
        }
        tm0 = fmaxf(tm0, __shfl_xor_sync(0xffffffffu, tm0, 1));
        tm0 = fmaxf(tm0, __shfl_xor_sync(0xffffffffu, tm0, 2));
        tm1 = fmaxf(tm1, __shfl_xor_sync(0xffffffffu, tm1, 1));
        tm1 = fmaxf(tm1, __shfl_xor_sync(0xffffffffu, tm1, 2));

        float nm0 = fmaxf(m0, tm0), nm1 = fmaxf(m1, tm1);
        float al0 = __expf(m0 - nm0), al1 = __expf(m1 - nm1);

        float ts0 = 0.f, ts1 = 0.f;
#pragma unroll
        for (int nt = 0; nt < 8; nt++) {
            sfC[nt][0] = __expf(sfC[nt][0] - nm0); ts0 += sfC[nt][0];
            sfC[nt][1] = __expf(sfC[nt][1] - nm0); ts0 += sfC[nt][1];
            sfC[nt][2] = __expf(sfC[nt][2] - nm1); ts1 += sfC[nt][2];
            sfC[nt][3] = __expf(sfC[nt][3] - nm1); ts1 += sfC[nt][3];
        }
        ts0 += __shfl_xor_sync(0xffffffffu, ts0, 1);
        ts0 += __shfl_xor_sync(0xffffffffu, ts0, 2);
        ts1 += __shfl_xor_sync(0xffffffffu, ts1, 1);
        ts1 += __shfl_xor_sync(0xffffffffu, ts1, 2);

        l0 = l0 * al0 + ts0;  l1 = l1 * al1 + ts1;
        m0 = nm0;             m1 = nm1;

#pragma unroll
        for (int nt = 0; nt < 16; nt++) {
            acc[nt][0] *= al0; acc[nt][1] *= al0;
            acc[nt][2] *= al1; acc[nt][3] *= al1;
        }

        // write P tile (warp-private rows) as tf32
#pragma unroll
        for (int nt = 0; nt < 8; nt++) {
            Ps[qbase + g][nt * 8 + 2 * tg]         = f2tf(sfC[nt][0]);
            Ps[qbase + g][nt * 8 + 2 * tg + 1]     = f2tf(sfC[nt][1]);
            Ps[qbase + g + 8][nt * 8 + 2 * tg]     = f2tf(sfC[nt][2]);
            Ps[qbase + g + 8][nt * 8 + 2 * tg + 1] = f2tf(sfC[nt][3]);
        }
        __syncwarp();

        cpa_wait1();                                      // drain B_{kt-1} = V(kt)
        __syncthreads();                                  // bar_c: V(kt) visible

        // acc += P @ V  (M=16, N=128, K=64)
#pragma unroll
        for (int ks = 0; ks < 8; ks++) {
            uint32_t a[4];
            ldsm_x4(a, sP + 4u * (rowAq * PLD + ks * 8 + colA));
#pragma unroll
            for (int nt = 0; nt < 16; nt++) {
                uint32_t bb[2];
                bb[0] = Vs[ks * 8 + tg][nt * 8 + g];
                bb[1] = Vs[ks * 8 + tg + 4][nt * 8 + g];
                mma_tf32(acc[nt], a, bb);
            }
        }

        __syncthreads();                                  // bar_d: V WAR
        // commit B_kt = V(kt+1) (empty group if out of range)
        if (kt + 1 < NKT) {
            size_t rowV1 = (size_t)(b * SEQ + (kt + 1) * 64);
#pragma unroll
            for (int p = 0; p < 8; p++) {
                int rr = ldr + p * 8;
                cpa16(sVb + 4u * (rr * ALD + ldc),
                      Vp + (rowV1 + rr) * DMODEL + colH + ldc);
            }
        }
        cpa_commit();
    };

    for (int kt = 0; kt < NKT; kt += 2) {
        step(kt,     sfA, sfB, sK1, sK0);   // S(kt+1) from buf1, refill K(kt+2)->buf0
        step(kt + 1, sfB, sfA, sK0, sK1);   // S(kt+2) from buf0, refill K(kt+3)->buf1
    }

    // epilogue: normalize, round to tf32 (gemm_o consumes raw), write out
    float inv0 = 1.f / l0, inv1 = 1.f / l1;
    size_t r0 = rowQ0 + qbase + g;
    size_t r1 = r0 + 8;
#pragma unroll
    for (int nt = 0; nt < 16; nt++) {
        int c = colH + nt * 8 + 2 * tg;
        float2 w0 = make_float2(__uint_as_float(f2tf(acc[nt][0] * inv0)),
                                __uint_as_float(f2tf(acc[nt][1] * inv0)));
        float2 w1 = make_float2(__uint_as_float(f2tf(acc[nt][2] * inv1)),
                                __uint_as_float(f2tf(acc[nt][3] * inv1)));
        *(float2*)&O[r0 * DMODEL + c] = w0;
        *(float2*)&O[r1 * DMODEL + c] = w1;
    }
}

// ---------------- launch ----------------
extern "C" void kernel_launch(void* const* d_in, const int* in_sizes, int n_in,
                              void* d_out, int out_size)
{
    const float* query  = (const float*)d_in[0];
    const float* key_in = (const float*)d_in[1];
    const float* value  = (const float*)d_in[2];
    const float* Wq = (const float*)d_in[3];
    const float* bq = (const float*)d_in[4];
    const float* Wk = (const float*)d_in[5];
    const float* bk = (const float*)d_in[6];
    const float* Wv = (const float*)d_in[7];
    const float* bv = (const float*)d_in[8];
    const float* Wo = (const float*)d_in[9];
    const float* bo = (const float*)d_in[10];
    float* out = (float*)d_out;

    float *gq, *gk, *gv, *ga;
    float *xq, *xk, *xv, *wq, *wk, *wv, *wo;
    cudaGetSymbolAddress((void**)&gq, g_q);
    cudaGetSymbolAddress((void**)&gk, g_k);
    cudaGetSymbolAddress((void**)&gv, g_v);
    cudaGetSymbolAddress((void**)&ga, g_att);
    cudaGetSymbolAddress((void**)&xq, g_xq);
    cudaGetSymbolAddress((void**)&xk, g_xk);
    cudaGetSymbolAddress((void**)&xv, g_xv);
    cudaGetSymbolAddress((void**)&wq, g_wq);
    cudaGetSymbolAddress((void**)&wk, g_wk);
    cudaGetSymbolAddress((void**)&wv, g_wv);
    cudaGetSymbolAddress((void**)&wo, g_wo);

    cudaFuncSetAttribute(attn_kernel,
                         cudaFuncAttributeMaxDynamicSharedMemorySize, ATT_SMEM_BYTES);
    cudaFuncSetAttribute(gemm_qkv,
                         cudaFuncAttributeMaxDynamicSharedMemorySize, GEMM_SMEM_BYTES);
    cudaFuncSetAttribute(gemm_o,
                         cudaFuncAttributeMaxDynamicSharedMemorySize, GEMM_SMEM_BYTES);

    const float qscale = 0.08838834764831845f;   // 1/sqrt(128)

    // prepass: tf32-round inputs + weights
    {
        dim3 gi((MROWS * DMODEL) / (4 * 256), 3);    // (8192, 3)
        round_inputs<<<gi, 256>>>(query, key_in, value, xq, xk, xv);
        dim3 gw((DMODEL * DMODEL) / (4 * 256), 4);   // (4096, 4)
        round_weights<<<gw, 256>>>(Wq, Wk, Wv, Wo, wq, wk, wv, wo);
    }

    dim3 qkv_grid(DMODEL / 128, MROWS / 128, 3);   // (16, 32, 3) = 1536 CTAs
    gemm_qkv<<<qkv_grid, 256, GEMM_SMEM_BYTES>>>(xq, xk, xv,
                                                 wq, bq, wk, bk, wv, bv,
                                                 gq, gk, gv, qscale);

    attn_kernel<<<dim3(SEQ / 128, NHEADS, BATCH), 256, ATT_SMEM_BYTES>>>(gq, gk, gv, ga);

    gemm_o<<<dim3(DMODEL / 128, MROWS / 128), 256, GEMM_SMEM_BYTES>>>(ga, wo, bo, out);
}

// round 14
// speedup vs baseline: 1.2747x; 1.0677x over previous
#include <cuda_runtime.h>
#include <cstdint>
#include <cstdio>

#define DMODEL 2048
#define NHEADS 16
#define HDIM   128
#define BATCH  2
#define SEQ    2048
#define MROWS  (BATCH*SEQ)   // 4096

// ---------------- scratch (device globals: allocation-free) ----------------
__device__ float g_q[(size_t)MROWS * DMODEL];
__device__ float g_k[(size_t)MROWS * DMODEL];
__device__ float g_v[(size_t)MROWS * DMODEL];
__device__ float g_att[(size_t)MROWS * DMODEL];
// tf32-rounded copies (prepass outputs)
__device__ float g_xq[(size_t)MROWS * DMODEL];
__device__ float g_xk[(size_t)MROWS * DMODEL];
__device__ float g_xv[(size_t)MROWS * DMODEL];
__device__ float g_wq[(size_t)DMODEL * DMODEL];
__device__ float g_wk[(size_t)DMODEL * DMODEL];
__device__ float g_wv[(size_t)DMODEL * DMODEL];
__device__ float g_wo[(size_t)DMODEL * DMODEL];

// ---------------- helpers ----------------
__device__ __forceinline__ uint32_t f2tf(float x) {
    uint32_t r;
    asm("cvt.rna.tf32.f32 %0, %1;" : "=r"(r) : "f"(x));
    return r;
}

__device__ __forceinline__ void mma_tf32(float* c, const uint32_t* a, const uint32_t* b) {
    asm("mma.sync.aligned.m16n8k8.row.col.f32.tf32.tf32.f32 "
        "{%0,%1,%2,%3}, {%4,%5,%6,%7}, {%8,%9}, {%0,%1,%2,%3};"
        : "+f"(c[0]), "+f"(c[1]), "+f"(c[2]), "+f"(c[3])
        : "r"(a[0]), "r"(a[1]), "r"(a[2]), "r"(a[3]),
          "r"(b[0]), "r"(b[1]));
}

__device__ __forceinline__ void ldsm_x4(uint32_t* r, uint32_t addr) {
    asm volatile("ldmatrix.sync.aligned.m8n8.x4.shared.b16 {%0,%1,%2,%3}, [%4];"
        : "=r"(r[0]), "=r"(r[1]), "=r"(r[2]), "=r"(r[3]) : "r"(addr));
}

__device__ __forceinline__ void cpa16(uint32_t dst, const void* src) {
    asm volatile("cp.async.cg.shared.global [%0], [%1], 16;" :: "r"(dst), "l"(src));
}
__device__ __forceinline__ void cpa_commit() {
    asm volatile("cp.async.commit_group;" ::: "memory");
}
__device__ __forceinline__ void cpa_wait0() {
    asm volatile("cp.async.wait_group 0;" ::: "memory");
}
__device__ __forceinline__ void cpa_wait1() {
    asm volatile("cp.async.wait_group 1;" ::: "memory");
}

// ---------------- prepass: tf32 rounding of inputs / weights ----------------
__global__ void __launch_bounds__(256) round_inputs(
    const float* __restrict__ q, const float* __restrict__ k, const float* __restrict__ v,
    float* __restrict__ oq, float* __restrict__ ok, float* __restrict__ ov)
{
    size_t idx = ((size_t)blockIdx.x * 256 + threadIdx.x) * 4;
    const float* s = (blockIdx.y == 0) ? q : (blockIdx.y == 1) ? k : v;
    float*       d = (blockIdx.y == 0) ? oq : (blockIdx.y == 1) ? ok : ov;
    float4 t = *(const float4*)(s + idx);
    uint4 u = make_uint4(f2tf(t.x), f2tf(t.y), f2tf(t.z), f2tf(t.w));
    *(uint4*)(d + idx) = u;
}

__global__ void __launch_bounds__(256) round_weights(
    const float* __restrict__ wq, const float* __restrict__ wk,
    const float* __restrict__ wv, const float* __restrict__ wo,
    float* __restrict__ oq, float* __restrict__ ok,
    float* __restrict__ ov, float* __restrict__ oo)
{
    size_t idx = ((size_t)blockIdx.x * 256 + threadIdx.x) * 4;
    const float* s = (blockIdx.y == 0) ? wq : (blockIdx.y == 1) ? wk : (blockIdx.y == 2) ? wv : wo;
    float*       d = (blockIdx.y == 0) ? oq : (blockIdx.y == 1) ? ok : (blockIdx.y == 2) ? ov : oo;
    float4 t = *(const float4*)(s + idx);
    uint4 u = make_uint4(f2tf(t.x), f2tf(t.y), f2tf(t.z), f2tf(t.w));
    *(uint4*)(d + idx) = u;
}

// ---------------- GEMM body: C = (A @ W^T + bias) * scale ----------------
#define GT_K 32
#define GLD  36
#define GSTG (128*GLD)
#define GEMM_SMEM_BYTES (4*GSTG*4)   // 73728 B -> 2 CTAs/SM

template<bool ROUND>
__device__ __forceinline__ void gemm_body(
    const float* __restrict__ A, const float* __restrict__ W,
    const float* __restrict__ bias, float* __restrict__ C, float scale)
{
    extern __shared__ uint32_t gsm[];
    const uint32_t sbase = (uint32_t)__cvta_generic_to_shared(gsm);

    const int tid  = threadIdx.x;
    const int ctaN = blockIdx.x * 128;
    const int ctaM = blockIdx.y * 128;

    const int warp = tid >> 5, lane = tid & 31;
    const int g = lane >> 2, tg = lane & 3;
    const int wm = (warp & 1) * 64;
    const int wn = (warp >> 1) * 32;

    const int rowA = wm + (lane & 7) + ((lane & 8) ? 8 : 0);
    const int colA = (lane & 16) ? 4 : 0;
    const int rowB = wn + (lane & 7) + ((lane & 16) ? 8 : 0);
    const int colB = (lane & 8) ? 4 : 0;

    const int lr = tid >> 3;
    const int lc = (tid & 7) * 4;

    const float* Abase = A + (size_t)(ctaM + lr) * DMODEL + lc;
    const float* Wbase = W + (size_t)(ctaN + lr) * DMODEL + lc;

    float acc[4][4][4];
#pragma unroll
    for (int mt = 0; mt < 4; mt++)
#pragma unroll
        for (int nt = 0; nt < 4; nt++)
#pragma unroll
            for (int j = 0; j < 4; j++) acc[mt][nt][j] = 0.f;

    const int nk = DMODEL / GT_K;

    auto issue = [&](int kt, int s) {
        const float* An = Abase + (size_t)kt * GT_K;
        const float* Wn = Wbase + (size_t)kt * GT_K;
        uint32_t dA = sbase + 4u * ((uint32_t)(s * 2 * GSTG) + lr * GLD + lc);
        uint32_t dW = dA + 4u * (uint32_t)GSTG;
#pragma unroll
        for (int p = 0; p < 4; p++) {
            cpa16(dA + 4u * (p * 32 * GLD), An + (size_t)(p * 32) * DMODEL);
            cpa16(dW + 4u * (p * 32 * GLD), Wn + (size_t)(p * 32) * DMODEL);
        }
        cpa_commit();
    };

    issue(0, 0);
    cpa_wait0();
    __syncthreads();

    for (int kt = 0; kt < nk; kt++) {
        const int cur = kt & 1;
        const bool pre = (kt + 1 < nk);
        if (pre) issue(kt + 1, cur ^ 1);

        const uint32_t sA = sbase + (uint32_t)(cur * 2 * GSTG) * 4u;
        const uint32_t sW = sA + (uint32_t)GSTG * 4u;

#pragma unroll
        for (int ks = 0; ks < 4; ks++) {
            uint32_t a[4][4];
#pragma unroll
            for (int mt = 0; mt < 4; mt++)
                ldsm_x4(a[mt], sA + 4u * ((rowA + mt * 16) * GLD + ks * 8 + colA));
            uint32_t bfr[4][2];
#pragma unroll
            for (int ntp = 0; ntp < 2; ntp++) {
                uint32_t t[4];
                ldsm_x4(t, sW + 4u * ((rowB + ntp * 16) * GLD + ks * 8 + colB));
                bfr[2 * ntp][0] = t[0];  bfr[2 * ntp][1] = t[1];
                bfr[2 * ntp + 1][0] = t[2];  bfr[2 * ntp + 1][1] = t[3];
            }
#pragma unroll
            for (int mt = 0; mt < 4; mt++)
#pragma unroll
                for (int nt = 0; nt < 4; nt++)
                    mma_tf32(acc[mt][nt], a[mt], bfr[nt]);
        }

        if (pre) cpa_wait0();
        __syncthreads();
    }

#pragma unroll
    for (int mt = 0; mt < 4; mt++) {
        int r0 = ctaM + wm + mt * 16 + g;
        int r1 = r0 + 8;
#pragma unroll
        for (int nt = 0; nt < 4; nt++) {
            int c = ctaN + wn + nt * 8 + 2 * tg;
            float b0 = bias[c], b1 = bias[c + 1];
            float v00 = (acc[mt][nt][0] + b0) * scale;
            float v01 = (acc[mt][nt][1] + b1) * scale;
            float v10 = (acc[mt][nt][2] + b0) * scale;
            float v11 = (acc[mt][nt][3] + b1) * scale;
            if (ROUND) {
                v00 = __uint_as_float(f2tf(v00));
                v01 = __uint_as_float(f2tf(v01));
                v10 = __uint_as_float(f2tf(v10));
                v11 = __uint_as_float(f2tf(v11));
            }
            *(float2*)&C[(size_t)r0 * DMODEL + c] = make_float2(v00, v01);
            *(float2*)&C[(size_t)r1 * DMODEL + c] = make_float2(v10, v11);
        }
    }
}

__global__ void __launch_bounds__(256, 2) gemm_qkv(
    const float* __restrict__ q_in, const float* __restrict__ k_in, const float* __restrict__ v_in,
    const float* __restrict__ Wq, const float* __restrict__ bq,
    const float* __restrict__ Wk, const float* __restrict__ bk,
    const float* __restrict__ Wv, const float* __restrict__ bv,
    float* __restrict__ Cq, float* __restrict__ Ck, float* __restrict__ Cv,
    float qscale)
{
    const int z = blockIdx.z;
    const float* A   = (z == 0) ? q_in : (z == 1) ? k_in : v_in;
    const float* W   = (z == 0) ? Wq   : (z == 1) ? Wk   : Wv;
    const float* bia = (z == 0) ? bq   : (z == 1) ? bk   : bv;
    float*       C   = (z == 0) ? Cq   : (z == 1) ? Ck   : Cv;
    float        s   = (z == 0) ? qscale : 1.0f;
    gemm_body<true>(A, W, bia, C, s);
}

__global__ void __launch_bounds__(256, 2) gemm_o(
    const float* __restrict__ A, const float* __restrict__ W,
    const float* __restrict__ bias, float* __restrict__ C)
{
    gemm_body<false>(A, W, bias, C, 1.0f);
}

// ---------------- Flash attention v2: qtile=64, 4 warps, 2 CTAs/SM ----------------
// smem = Q(64x132) + K(64x132) + V(64x132) = 99 KB -> two CTAs co-resident;
// one CTA's softmax overlaps the other's MMAs. P tile never touches smem:
// A-fragments for PV are built from score C-fragments via warp shuffles.
#define ALD 132   // 128 + 4 pad
#define AK_OFF (64*ALD)
#define AV_OFF (128*ALD)
#define ATT_SMEM_WORDS (192*ALD)
#define ATT_SMEM_BYTES (ATT_SMEM_WORDS * 4)   // 101376 B
#define NKT (SEQ/64)

__global__ void __launch_bounds__(128, 2) attn_kernel(
    const float* __restrict__ Q, const float* __restrict__ Kp,
    const float* __restrict__ Vp, float* __restrict__ O)
{
    extern __shared__ uint32_t sm[];
    uint32_t (*Vs)[ALD] = (uint32_t(*)[ALD])(sm + AV_OFF);

    const uint32_t sbase = (uint32_t)__cvta_generic_to_shared(sm);
    const uint32_t sQ = sbase;
    const uint32_t sK = sbase + 4u * AK_OFF;

    const int tid  = threadIdx.x;
    const int qt = blockIdx.x, h = blockIdx.y, b = blockIdx.z;
    const int warp = tid >> 5, lane = tid & 31, g = lane >> 2, tg = lane & 3;
    const int qbase = warp * 16;

    const int rowAq = qbase + (lane & 7) + ((lane & 8) ? 8 : 0);
    const int colA  = (lane & 16) ? 4 : 0;
    const int rowK  = (lane & 7) + ((lane & 16) ? 8 : 0);
    const int colK  = (lane & 8) ? 4 : 0;
    // P-shuffle source lane: holder of P[g][8ks+tg] is lane 4g + (tg>>1)
    const int psrc  = (lane & 28) | ((lane >> 1) & 1);

    const size_t rowQ0 = (size_t)(b * SEQ + qt * 64);
    const int colH = h * HDIM;

    const int ldr = tid >> 5;       // 0..3
    const int ldc = lane * 4;       // 0..124 (words)

    // prologue: Q (64 rows), K0, V0 — one group
#pragma unroll
    for (int p = 0; p < 16; p++) {
        int rr = ldr + p * 4;
        cpa16(sQ + 4u * (rr * ALD + ldc), Q + (rowQ0 + rr) * DMODEL + colH + ldc);
    }
    {
        size_t rowK0 = (size_t)(b * SEQ);
#pragma unroll
        for (int p = 0; p < 16; p++) {
            int rr = ldr + p * 4;
            cpa16(sK + 4u * (rr * ALD + ldc), Kp + (rowK0 + rr) * DMODEL + colH + ldc);
            cpa16(sbase + 4u * (AV_OFF + rr * ALD + ldc), Vp + (rowK0 + rr) * DMODEL + colH + ldc);
        }
    }
    cpa_commit();
    cpa_wait0();
    __syncthreads();

    float acc[16][4];
#pragma unroll
    for (int nt = 0; nt < 16; nt++)
#pragma unroll
        for (int j = 0; j < 4; j++) acc[nt][j] = 0.f;

    float m0 = -1e30f, m1 = -1e30f, l0 = 0.f, l1 = 0.f;

    for (int kt = 0; kt < NKT; kt++) {
        const bool pre = (kt + 1 < NKT);
        const size_t rowKn = (size_t)(b * SEQ + (kt + 1) * 64);

        // S = Q * K^T  (M=16 per warp, N=64, K=128); 1/sqrt(dh) folded into Q
        float sf[8][4];
#pragma unroll
        for (int nt = 0; nt < 8; nt++)
#pragma unroll
            for (int j = 0; j < 4; j++) sf[nt][j] = 0.f;

#pragma unroll
        for (int ks = 0; ks < 16; ks++) {
            uint32_t a[4];
            ldsm_x4(a, sQ + 4u * (rowAq * ALD + ks * 8 + colA));
            uint32_t bfr[8][2];
#pragma unroll
            for (int ntp = 0; ntp < 4; ntp++) {
                uint32_t t[4];
                ldsm_x4(t, sK + 4u * ((rowK + ntp * 16) * ALD + ks * 8 + colK));
                bfr[2 * ntp][0] = t[0];  bfr[2 * ntp][1] = t[1];
                bfr[2 * ntp + 1][0] = t[2];  bfr[2 * ntp + 1][1] = t[3];
            }
#pragma unroll
            for (int nt = 0; nt < 8; nt++)
                mma_tf32(sf[nt], a, bfr[nt]);
        }

        // K free -> refill with next K tile (hidden by softmax + PV below)
        __syncthreads();
        if (pre) {
#pragma unroll
            for (int p = 0; p < 16; p++) {
                int rr = ldr + p * 4;
                cpa16(sK + 4u * (rr * ALD + ldc),
                      Kp + (rowKn + rr) * DMODEL + colH + ldc);
            }
            cpa_commit();
            cpa_wait1();   // current V tile (older group) is complete
        } else {
            cpa_wait0();
        }
        __syncthreads();

        // ---- online softmax (rows qbase+g and qbase+g+8) ----
        float tm0 = -1e30f, tm1 = -1e30f;
#pragma unroll
        for (int nt = 0; nt < 8; nt++) {
            tm0 = fmaxf(tm0, fmaxf(sf[nt][0], sf[nt][1]));
            tm1 = fmaxf(tm1, fmaxf(sf[nt][2], sf[nt][3]));
        }
        tm0 = fmaxf(tm0, __shfl_xor_sync(0xffffffffu, tm0, 1));
        tm0 = fmaxf(tm0, __shfl_xor_sync(0xffffffffu, tm0, 2));
        tm1 = fmaxf(tm1, __shfl_xor_sync(0xffffffffu, tm1, 1));
        tm1 = fmaxf(tm1, __shfl_xor_sync(0xffffffffu, tm1, 2));

        float nm0 = fmaxf(m0, tm0), nm1 = fmaxf(m1, tm1);
        float al0 = __expf(m0 - nm0), al1 = __expf(m1 - nm1);

        float ts0 = 0.f, ts1 = 0.f;
#pragma unroll
        for (int nt = 0; nt < 8; nt++) {
            sf[nt][0] = __expf(sf[nt][0] - nm0); ts0 += sf[nt][0];
            sf[nt][1] = __expf(sf[nt][1] - nm0); ts0 += sf[nt][1];
            sf[nt][2] = __expf(sf[nt][2] - nm1); ts1 += sf[nt][2];
            sf[nt][3] = __expf(sf[nt][3] - nm1); ts1 += sf[nt][3];
        }
        ts0 += __shfl_xor_sync(0xffffffffu, ts0, 1);
        ts0 += __shfl_xor_sync(0xffffffffu, ts0, 2);
        ts1 += __shfl_xor_sync(0xffffffffu, ts1, 1);
        ts1 += __shfl_xor_sync(0xffffffffu, ts1, 2);

        l0 = l0 * al0 + ts0;  l1 = l1 * al1 + ts1;
        m0 = nm0;             m1 = nm1;

#pragma unroll
        for (int nt = 0; nt < 16; nt++) {
            acc[nt][0] *= al0; acc[nt][1] *= al0;
            acc[nt][2] *= al1; acc[nt][3] *= al1;
        }

        // P as tf32 bits (same values as the old smem round-trip)
        uint32_t pb[8][4];
#pragma unroll
        for (int nt = 0; nt < 8; nt++) {
            pb[nt][0] = f2tf(sf[nt][0]);
            pb[nt][1] = f2tf(sf[nt][1]);
            pb[nt][2] = f2tf(sf[nt][2]);
            pb[nt][3] = f2tf(sf[nt][3]);
        }

        // acc += P @ V  (M=16, N=128, K=64); P A-frags via shuffle transpose
        const bool odd = (tg & 1);
#pragma unroll
        for (int ks = 0; ks < 8; ks++) {
            uint32_t u0 = __shfl_sync(0xffffffffu, pb[ks][0], psrc);
            uint32_t u1 = __shfl_sync(0xffffffffu, pb[ks][1], psrc);
            uint32_t u2 = __shfl_sync(0xffffffffu, pb[ks][2], psrc);
            uint32_t u3 = __shfl_sync(0xffffffffu, pb[ks][3], psrc);
            uint32_t w0 = __shfl_sync(0xffffffffu, pb[ks][0], psrc + 2);
            uint32_t w1 = __shfl_sync(0xffffffffu, pb[ks][1], psrc + 2);
            uint32_t w2 = __shfl_sync(0xffffffffu, pb[ks][2], psrc + 2);
            uint32_t w3 = __shfl_sync(0xffffffffu, pb[ks][3], psrc + 2);
            uint32_t a[4];
            a[0] = odd ? u1 : u0;
            a[1] = odd ? u3 : u2;
            a[2] = odd ? w1 : w0;
            a[3] = odd ? w3 : w2;
#pragma unroll
            for (int nt = 0; nt < 16; nt++) {
                uint32_t bb[2];
                bb[0] = Vs[ks * 8 + tg][nt * 8 + g];
                bb[1] = Vs[ks * 8 + tg + 4][nt * 8 + g];
                mma_tf32(acc[nt], a, bb);
            }
        }

        // V free -> refill with next V tile (hidden by next iteration's S-MMA)
        __syncthreads();
        if (pre) {
#pragma unroll
            for (int p = 0; p < 16; p++) {
                int rr = ldr + p * 4;
                cpa16(sbase + 4u * (AV_OFF + rr * ALD + ldc),
                      Vp + (rowKn + rr) * DMODEL + colH + ldc);
            }
            cpa_commit();
            cpa_wait1();   // next K tile (older group) is complete
        } else {
            cpa_wait0();
        }
        __syncthreads();
    }

    // epilogue: normalize, round to tf32 (gemm_o consumes raw), write out
    float inv0 = 1.f / l0, inv1 = 1.f / l1;
    size_t r0 = rowQ0 + qbase + g;
    size_t r1 = r0 + 8;
#pragma unroll
    for (int nt = 0; nt < 16; nt++) {
        int c = colH + nt * 8 + 2 * tg;
        float2 w0 = make_float2(__uint_as_float(f2tf(acc[nt][0] * inv0)),
                                __uint_as_float(f2tf(acc[nt][1] * inv0)));
        float2 w1 = make_float2(__uint_as_float(f2tf(acc[nt][2] * inv1)),
                                __uint_as_float(f2tf(acc[nt][3] * inv1)));
        *(float2*)&O[r0 * DMODEL + c] = w0;
        *(float2*)&O[r1 * DMODEL + c] = w1;
    }
}

// ---------------- launch ----------------
extern "C" void kernel_launch(void* const* d_in, const int* in_sizes, int n_in,
                              void* d_out, int out_size)
{
    const float* query  = (const float*)d_in[0];
    const float* key_in = (const float*)d_in[1];
    const float* value  = (const float*)d_in[2];
    const float* Wq = (const float*)d_in[3];
    const float* bq = (const float*)d_in[4];
    const float* Wk = (const float*)d_in[5];
    const float* bk = (const float*)d_in[6];
    const float* Wv = (const float*)d_in[7];
    const float* bv = (const float*)d_in[8];
    const float* Wo = (const float*)d_in[9];
    const float* bo = (const float*)d_in[10];
    float* out = (float*)d_out;

    float *gq, *gk, *gv, *ga;
    float *xq, *xk, *xv, *wq, *wk, *wv, *wo;
    cudaGetSymbolAddress((void**)&gq, g_q);
    cudaGetSymbolAddress((void**)&gk, g_k);
    cudaGetSymbolAddress((void**)&gv, g_v);
    cudaGetSymbolAddress((void**)&ga, g_att);
    cudaGetSymbolAddress((void**)&xq, g_xq);
    cudaGetSymbolAddress((void**)&xk, g_xk);
    cudaGetSymbolAddress((void**)&xv, g_xv);
    cudaGetSymbolAddress((void**)&wq, g_wq);
    cudaGetSymbolAddress((void**)&wk, g_wk);
    cudaGetSymbolAddress((void**)&wv, g_wv);
    cudaGetSymbolAddress((void**)&wo, g_wo);

    cudaFuncSetAttribute(attn_kernel,
                         cudaFuncAttributeMaxDynamicSharedMemorySize, ATT_SMEM_BYTES);
    cudaFuncSetAttribute(gemm_qkv,
                         cudaFuncAttributeMaxDynamicSharedMemorySize, GEMM_SMEM_BYTES);
    cudaFuncSetAttribute(gemm_o,
                         cudaFuncAttributeMaxDynamicSharedMemorySize, GEMM_SMEM_BYTES);

    const float qscale = 0.08838834764831845f;   // 1/sqrt(128)

    // prepass: tf32-round inputs + weights
    {
        dim3 gi((MROWS * DMODEL) / (4 * 256), 3);    // (8192, 3)
        round_inputs<<<gi, 256>>>(query, key_in, value, xq, xk, xv);
        dim3 gw((DMODEL * DMODEL) / (4 * 256), 4);   // (4096, 4)
        round_weights<<<gw, 256>>>(Wq, Wk, Wv, Wo, wq, wk, wv, wo);
    }

    dim3 qkv_grid(DMODEL / 128, MROWS / 128, 3);   // (16, 32, 3) = 1536 CTAs
    gemm_qkv<<<qkv_grid, 256, GEMM_SMEM_BYTES>>>(xq, xk, xv,
                                                 wq, bq, wk, bk, wv, bv,
                                                 gq, gk, gv, qscale);

    attn_kernel<<<dim3(SEQ / 64, NHEADS, BATCH), 128, ATT_SMEM_BYTES>>>(gq, gk, gv, ga);

    gemm_o<<<dim3(DMODEL / 128, MROWS / 128), 256, GEMM_SMEM_BYTES>>>(ga, wo, bo, out);
}